// round 1
// baseline (speedup 1.0000x reference)
#include <cuda_runtime.h>
#include <math.h>

// Problem dims (fixed by the reference)
#define BB 4
#define LL 4096
#define EE 1024
#define HH 16
#define DD 64
#define BH (BB*HH)       // 64
#define MM (BB*LL)       // 16384
#define LSPLIT 8

// ---------------- scratch (static device allocations; allowed) --------------
__device__ float g_phiQ[BB*LL*EE];          // elu(Q)+1, [B,L,E]
__device__ float g_phiK[BB*LL*EE];          // elu(K)+1
__device__ float g_V  [BB*LL*EE];           // V
__device__ float g_ctx[BB*LL*EE];           // context before Wo
__device__ float g_S  [BH*DD*DD];           // [bh,64,64]
__device__ float g_Z  [BH*DD];              // [bh,64]
__device__ float g_Spart[LSPLIT*BH*DD*DD];  // deterministic split-L partials
__device__ float g_Zpart[LSPLIT*BH*DD];

// ---------------- 128x128x16 fp32 GEMM: C[m,n] = A[m,:]·W[n,:] + bias[n] ----
// A: [M,E] row-major, W: [N,E] row-major (einsum "ble,fe->blf"), N=E=1024.
// act=1 applies elu(x)+1 = (x>0 ? x+1 : exp(x)).
__device__ __forceinline__ void gemm_body(const float* __restrict__ A,
                                          const float* __restrict__ W,
                                          const float* __restrict__ bias,
                                          float* __restrict__ C,
                                          int act)
{
    __shared__ float As[16][132];   // padded: conflict-free transposed stores
    __shared__ float Bs[16][132];   // 132*4B = 528B rows keep 16B alignment

    const int tid = threadIdx.x;           // 256 threads
    const int tx  = tid & 15;
    const int ty  = tid >> 4;
    const int m0  = blockIdx.y * 128;
    const int n0  = blockIdx.x * 128;

    float acc[8][8];
    #pragma unroll
    for (int i = 0; i < 8; i++)
        #pragma unroll
        for (int j = 0; j < 8; j++) acc[i][j] = 0.f;

    for (int k0 = 0; k0 < EE; k0 += 16) {
        // load A tile [128 rows x 16 k] and W tile, 2 float4 per thread each.
        // f = tid + 256*t -> lanes cover 64B-contiguous row chunks (coalesced)
        #pragma unroll
        for (int t = 0; t < 2; t++) {
            int f   = tid + 256 * t;        // 0..511
            int row = f >> 2;               // 0..127
            int cg  = f & 3;                // float4 group within 16 k's
            float4 va = *(const float4*)&A[(size_t)(m0 + row) * EE + k0 + cg * 4];
            As[cg*4+0][row] = va.x;
            As[cg*4+1][row] = va.y;
            As[cg*4+2][row] = va.z;
            As[cg*4+3][row] = va.w;
            float4 vb = *(const float4*)&W[(size_t)(n0 + row) * EE + k0 + cg * 4];
            Bs[cg*4+0][row] = vb.x;
            Bs[cg*4+1][row] = vb.y;
            Bs[cg*4+2][row] = vb.z;
            Bs[cg*4+3][row] = vb.w;
        }
        __syncthreads();

        #pragma unroll
        for (int k = 0; k < 16; k++) {
            float ra[8], rb[8];
            *(float4*)&ra[0] = *(const float4*)&As[k][ty * 8];
            *(float4*)&ra[4] = *(const float4*)&As[k][ty * 8 + 4];
            *(float4*)&rb[0] = *(const float4*)&Bs[k][tx * 8];
            *(float4*)&rb[4] = *(const float4*)&Bs[k][tx * 8 + 4];
            #pragma unroll
            for (int i = 0; i < 8; i++)
                #pragma unroll
                for (int j = 0; j < 8; j++)
                    acc[i][j] += ra[i] * rb[j];
        }
        __syncthreads();
    }

    // epilogue: bias (+ optional elu+1), vectorized stores
    #pragma unroll
    for (int i = 0; i < 8; i++) {
        int m = m0 + ty * 8 + i;
        #pragma unroll
        for (int j4 = 0; j4 < 2; j4++) {
            float4 v;
            float* vp = (float*)&v;
            #pragma unroll
            for (int c = 0; c < 4; c++) {
                int n = n0 + tx * 8 + j4 * 4 + c;
                float x = acc[i][j4 * 4 + c] + bias[n];
                if (act) x = (x > 0.f) ? (x + 1.f) : expf(x);
                vp[c] = x;
            }
            *(float4*)&C[(size_t)m * EE + n0 + tx * 8 + j4 * 4] = v;
        }
    }
}

// grid (8, 128, 3): z selects Q/K/V projection
__global__ void __launch_bounds__(256, 2)
qkv_kernel(const float* __restrict__ X,
           const float* __restrict__ Wq, const float* __restrict__ bq,
           const float* __restrict__ Wk, const float* __restrict__ bk,
           const float* __restrict__ Wv, const float* __restrict__ bv)
{
    int z = blockIdx.z;
    const float* W = (z == 0) ? Wq : (z == 1) ? Wk : Wv;
    const float* b = (z == 0) ? bq : (z == 1) ? bk : bv;
    float* C = (z == 0) ? g_phiQ : (z == 1) ? g_phiK : g_V;
    gemm_body(X, W, b, C, z < 2 ? 1 : 0);
}

// grid (8, 128): output projection on context
__global__ void __launch_bounds__(256, 2)
out_kernel(const float* __restrict__ Wo, const float* __restrict__ bo,
           float* __restrict__ out)
{
    gemm_body(g_ctx, Wo, bo, out, 0);
}

// ---------------- KV state: S = phiK^T V, Z = sum phiK (split over L) ------
// grid (BH, LSPLIT), 256 threads; deterministic partials, no atomics.
__global__ void __launch_bounds__(256)
kv_state_kernel()
{
    const int bh = blockIdx.x;
    const int p  = blockIdx.y;
    const int b  = bh / HH, h = bh % HH;
    const int lbase = p * (LL / LSPLIT);   // 512 rows per block

    const float* Kp = g_phiK + (size_t)b * LL * EE + h * DD;
    const float* Vp = g_V    + (size_t)b * LL * EE + h * DD;

    __shared__ float Ks[32][64];
    __shared__ float Vs[32][64];

    const int tid = threadIdx.x;
    const int tx = tid & 15, ty = tid >> 4;

    float acc[4][4];
    #pragma unroll
    for (int i = 0; i < 4; i++)
        #pragma unroll
        for (int j = 0; j < 4; j++) acc[i][j] = 0.f;
    float zacc[4] = {0.f, 0.f, 0.f, 0.f};

    for (int l0 = 0; l0 < LL / LSPLIT; l0 += 32) {
        #pragma unroll
        for (int t = 0; t < 2; t++) {
            int f   = tid + 256 * t;      // 0..511
            int row = f >> 4;             // 0..31
            int cg  = f & 15;             // float4 within 64 cols
            size_t g = (size_t)(lbase + l0 + row) * EE + cg * 4;
            *(float4*)&Ks[row][cg * 4] = *(const float4*)&Kp[g];
            *(float4*)&Vs[row][cg * 4] = *(const float4*)&Vp[g];
        }
        __syncthreads();
        #pragma unroll
        for (int ll = 0; ll < 32; ll++) {
            float rk[4], rv[4];
            *(float4*)rk = *(const float4*)&Ks[ll][ty * 4];
            *(float4*)rv = *(const float4*)&Vs[ll][tx * 4];
            #pragma unroll
            for (int i = 0; i < 4; i++)
                #pragma unroll
                for (int j = 0; j < 4; j++)
                    acc[i][j] += rk[i] * rv[j];
            if (tx == 0) {
                #pragma unroll
                for (int i = 0; i < 4; i++) zacc[i] += rk[i];
            }
        }
        __syncthreads();
    }

    float* Sp = g_Spart + ((size_t)p * BH + bh) * DD * DD;
    #pragma unroll
    for (int i = 0; i < 4; i++)
        #pragma unroll
        for (int j = 0; j < 4; j++)
            Sp[(ty * 4 + i) * DD + tx * 4 + j] = acc[i][j];
    if (tx == 0) {
        float* Zp = g_Zpart + ((size_t)p * BH + bh) * DD;
        #pragma unroll
        for (int i = 0; i < 4; i++) Zp[ty * 4 + i] = zacc[i];
    }
}

// fixed-order reduction of the L-split partials
__global__ void __launch_bounds__(256)
reduce_kernel()
{
    int idx = blockIdx.x * 256 + threadIdx.x;
    if (idx < BH * DD * DD) {
        float s = 0.f;
        #pragma unroll
        for (int pp = 0; pp < LSPLIT; pp++) s += g_Spart[(size_t)pp * BH * DD * DD + idx];
        g_S[idx] = s;
    }
    if (idx < BH * DD) {
        float s = 0.f;
        #pragma unroll
        for (int pp = 0; pp < LSPLIT; pp++) s += g_Zpart[(size_t)pp * BH * DD + idx];
        g_Z[idx] = s;
    }
}

// ---------------- context = (phiQ @ S) / (phiQ . Z + eps) -------------------
// grid (BH, L/64), 256 threads: 4 rows x 64 cols per pass, 16 passes.
__global__ void __launch_bounds__(256)
attn_out_kernel()
{
    const int bh = blockIdx.x;
    const int b  = bh / HH, h = bh % HH;

    __shared__ float Ss[DD][DD + 1];
    __shared__ float Zs[DD];
    __shared__ float Qs[4][DD];

    const int tid = threadIdx.x;
    const float* Sp = g_S + (size_t)bh * DD * DD;
    for (int idx = tid; idx < DD * DD; idx += 256)
        Ss[idx >> 6][idx & 63] = Sp[idx];
    if (tid < DD) Zs[tid] = g_Z[bh * DD + tid];
    __syncthreads();

    const int j    = tid & 63;
    const int rsub = tid >> 6;            // 0..3
    const int l0   = blockIdx.y * 64;
    const float* Qp = g_phiQ + (size_t)b * LL * EE + h * DD;
    float*       Cp = g_ctx  + (size_t)b * LL * EE + h * DD;

    for (int r = 0; r < 16; r++) {
        int lr = l0 + r * 4 + rsub;
        Qs[rsub][j] = Qp[(size_t)lr * EE + j];
        __syncthreads();
        float num = 0.f, den = 0.f;
        #pragma unroll
        for (int i = 0; i < DD; i++) {
            float q = Qs[rsub][i];
            num += q * Ss[i][j];
            den += q * Zs[i];
        }
        Cp[(size_t)lr * EE + j] = num / (den + 1e-6f);
        __syncthreads();
    }
}

// ---------------------------------------------------------------------------
extern "C" void kernel_launch(void* const* d_in, const int* in_sizes, int n_in,
                              void* d_out, int out_size)
{
    const float* X  = (const float*)d_in[0];
    const float* Wq = (const float*)d_in[1];
    const float* bq = (const float*)d_in[2];
    const float* Wk = (const float*)d_in[3];
    const float* bk = (const float*)d_in[4];
    const float* Wv = (const float*)d_in[5];
    const float* bv = (const float*)d_in[6];
    const float* Wo = (const float*)d_in[7];
    const float* bo = (const float*)d_in[8];
    float* out = (float*)d_out;

    dim3 gqkv(EE / 128, MM / 128, 3);
    qkv_kernel<<<gqkv, 256>>>(X, Wq, bq, Wk, bk, Wv, bv);

    kv_state_kernel<<<dim3(BH, LSPLIT), 256>>>();
    reduce_kernel<<<(BH * DD * DD + 255) / 256, 256>>>();
    attn_out_kernel<<<dim3(BH, LL / 64), 256>>>();

    dim3 gout(EE / 128, MM / 128, 1);
    out_kernel<<<gout, 256>>>(Wo, bo, out);
}

// round 10
// speedup vs baseline: 2.5355x; 2.5355x over previous
#include <cuda_runtime.h>
#include <cuda_bf16.h>
#include <cstdint>
#include <math.h>

// Problem dims (fixed by the reference)
#define BB 4
#define LL 4096
#define EE 1024
#define HH 16
#define DD 64
#define BH (BB*HH)       // 64
#define MM (BB*LL)       // 16384
#define LSPLIT 8

// GEMM tiling (bf16 split mma.sync)
#define BM 128
#define BN 128
#define BK 32                         // fp32-equivalent K per stage
#define PITCH 20                      // u32 per smem row (80B): conflict-free + 16B aligned
#define PLANE_U32 (128*PITCH)         // one operand plane (hi or lo): 10240 B
#define STAGE_U32 (4*PLANE_U32)       // Ahi,Alo,Bhi,Blo
#define SMEM_BYTES (2*STAGE_U32*4)    // double buffered = 81920 B
#define GT 256

// ---------------- scratch ---------------------------------------------------
__device__ __nv_bfloat16 g_Xhi[MM*EE], g_Xlo[MM*EE];
__device__ __nv_bfloat16 g_Whi[4][EE*EE], g_Wlo[4][EE*EE];   // q,k,v,o
__device__ __nv_bfloat16 g_Chi[MM*EE], g_Clo[MM*EE];         // ctx split
__device__ float g_phiQ[MM*EE];
__device__ float g_phiK[MM*EE];
__device__ float g_V  [MM*EE];
__device__ float g_S  [BH*DD*DD];
__device__ float g_Z  [BH*DD];
__device__ float g_Spart[LSPLIT*BH*DD*DD];
__device__ float g_Zpart[LSPLIT*BH*DD];

// ---------------- helpers ---------------------------------------------------
__device__ __forceinline__ void cpasync16(uint32_t dst, const void* src){
    asm volatile("cp.async.cg.shared.global [%0], [%1], 16;" :: "r"(dst), "l"(src) : "memory");
}
__device__ __forceinline__ void cp_commit(){
    asm volatile("cp.async.commit_group;" ::: "memory");
}
template<int N> __device__ __forceinline__ void cp_wait(){
    asm volatile("cp.async.wait_group %0;" :: "n"(N) : "memory");
}
__device__ __forceinline__ uint32_t smem_u32(const void* p){
    uint32_t a;
    asm("{ .reg .u64 t; cvta.to.shared.u64 t, %1; cvt.u32.u64 %0, t; }" : "=r"(a) : "l"(p));
    return a;
}
__device__ __forceinline__ void mma_bf16(float* c, const uint32_t* a, const uint32_t* b){
    asm volatile("mma.sync.aligned.m16n8k16.row.col.f32.bf16.bf16.f32 "
        "{%0,%1,%2,%3}, {%4,%5,%6,%7}, {%8,%9}, {%0,%1,%2,%3};"
        : "+f"(c[0]), "+f"(c[1]), "+f"(c[2]), "+f"(c[3])
        : "r"(a[0]), "r"(a[1]), "r"(a[2]), "r"(a[3]), "r"(b[0]), "r"(b[1]));
}

// ---------------- fp32 -> bf16 hi/lo split pre-pass -------------------------
// which: 0 = X, 1..4 = Wq,Wk,Wv,Wo
__global__ void __launch_bounds__(256)
split_kernel(const float* __restrict__ src, int which, int n)
{
    __nv_bfloat16* hi;
    __nv_bfloat16* lo;
    if (which == 0)      { hi = g_Xhi;     lo = g_Xlo;     }
    else                 { hi = g_Whi[which-1]; lo = g_Wlo[which-1]; }

    int i = (blockIdx.x * 256 + threadIdx.x) * 4;
    if (i >= n) return;
    float4 v = *(const float4*)(src + i);
    float x[4] = {v.x, v.y, v.z, v.w};
    uint32_t hp[2], lp[2];
    #pragma unroll
    for (int p = 0; p < 2; p++) {
        __nv_bfloat16 h0 = __float2bfloat16(x[2*p]);
        __nv_bfloat16 h1 = __float2bfloat16(x[2*p+1]);
        __nv_bfloat16 l0 = __float2bfloat16(x[2*p]   - __bfloat162float(h0));
        __nv_bfloat16 l1 = __float2bfloat16(x[2*p+1] - __bfloat162float(h1));
        hp[p] = ((uint32_t)__bfloat16_as_ushort(h1) << 16) | __bfloat16_as_ushort(h0);
        lp[p] = ((uint32_t)__bfloat16_as_ushort(l1) << 16) | __bfloat16_as_ushort(l0);
    }
    *(uint2*)(hi + i) = make_uint2(hp[0], hp[1]);
    *(uint2*)(lo + i) = make_uint2(lp[0], lp[1]);
}

// ---------------- bf16-split tensor-core GEMM body --------------------------
// C[m,n] = sum_k A[m,k]*W[n,k] + bias[n] via hi*hi + hi*lo + lo*hi.
__device__ __forceinline__ void load_tile(uint32_t st,
                                          const __nv_bfloat16* __restrict__ Ahi,
                                          const __nv_bfloat16* __restrict__ Alo,
                                          const __nv_bfloat16* __restrict__ Bhi,
                                          const __nv_bfloat16* __restrict__ Blo,
                                          int m0, int n0, int k0, int tid)
{
    #pragma unroll
    for (int t = 0; t < 2; t++) {
        int p   = tid + GT * t;          // 0..511
        int row = p >> 2;                // 0..127
        int cg  = p & 3;                 // 16B chunk within 64B row (32 bf16)
        uint32_t off = (uint32_t)(row * PITCH * 4 + cg * 16);
        size_t ga = (size_t)(m0 + row) * EE + k0 + cg * 8;
        size_t gb = (size_t)(n0 + row) * EE + k0 + cg * 8;
        cpasync16(st + off,                    Ahi + ga);
        cpasync16(st + PLANE_U32*4   + off,    Alo + ga);
        cpasync16(st + 2*PLANE_U32*4 + off,    Bhi + gb);
        cpasync16(st + 3*PLANE_U32*4 + off,    Blo + gb);
    }
}

__device__ __forceinline__ void mma_gemm(const __nv_bfloat16* __restrict__ Ahi,
                                         const __nv_bfloat16* __restrict__ Alo,
                                         const __nv_bfloat16* __restrict__ Bhi,
                                         const __nv_bfloat16* __restrict__ Blo,
                                         const float* __restrict__ bias,
                                         float* __restrict__ C, int act)
{
    extern __shared__ uint32_t smem[];
    const uint32_t sbase = smem_u32(smem);

    const int tid  = threadIdx.x;
    const int wid  = tid >> 5;
    const int lane = tid & 31;
    const int g    = lane >> 2;          // row within 8
    const int tg   = lane & 3;           // thread-in-group
    const int m0   = blockIdx.y * BM;
    const int n0   = blockIdx.x * BN;
    const int warpM = (wid >> 2) * 64;   // 2 warps in M
    const int warpN = (wid & 3) * 32;    // 4 warps in N

    float acc[4][4][4];
    #pragma unroll
    for (int i = 0; i < 4; i++)
        #pragma unroll
        for (int j = 0; j < 4; j++)
            #pragma unroll
            for (int r = 0; r < 4; r++) acc[i][j][r] = 0.f;

    load_tile(sbase, Ahi, Alo, Bhi, Blo, m0, n0, 0, tid);
    cp_commit();

    const int NIT = EE / BK;             // 32
    for (int it = 0; it < NIT; it++) {
        if (it + 1 < NIT) {
            load_tile(sbase + ((it + 1) & 1) * STAGE_U32 * 4,
                      Ahi, Alo, Bhi, Blo, m0, n0, (it + 1) * BK, tid);
            cp_commit();
            cp_wait<1>();
        } else {
            cp_wait<0>();
        }
        __syncthreads();

        const uint32_t* As_hi = smem + (it & 1) * STAGE_U32;
        const uint32_t* As_lo = As_hi + PLANE_U32;
        const uint32_t* Bs_hi = As_hi + 2 * PLANE_U32;
        const uint32_t* Bs_lo = As_hi + 3 * PLANE_U32;

        #pragma unroll
        for (int kb = 0; kb < 2; kb++) {         // two k16 blocks per BK=32
            const int kp = kb * 8;               // pair offset
            uint32_t ah[4][4], al[4][4], bh[4][2], bl[4][2];
            #pragma unroll
            for (int mt = 0; mt < 4; mt++) {
                int r0 = (warpM + mt * 16 + g) * PITCH;
                int r1 = r0 + 8 * PITCH;
                ah[mt][0] = As_hi[r0 + kp + tg];
                ah[mt][1] = As_hi[r1 + kp + tg];
                ah[mt][2] = As_hi[r0 + kp + tg + 4];
                ah[mt][3] = As_hi[r1 + kp + tg + 4];
                al[mt][0] = As_lo[r0 + kp + tg];
                al[mt][1] = As_lo[r1 + kp + tg];
                al[mt][2] = As_lo[r0 + kp + tg + 4];
                al[mt][3] = As_lo[r1 + kp + tg + 4];
            }
            #pragma unroll
            for (int nt = 0; nt < 4; nt++) {
                int rb = (warpN + nt * 8 + g) * PITCH;
                bh[nt][0] = Bs_hi[rb + kp + tg];
                bh[nt][1] = Bs_hi[rb + kp + tg + 4];
                bl[nt][0] = Bs_lo[rb + kp + tg];
                bl[nt][1] = Bs_lo[rb + kp + tg + 4];
            }
            #pragma unroll
            for (int mt = 0; mt < 4; mt++)
                #pragma unroll
                for (int nt = 0; nt < 4; nt++) {
                    mma_bf16(acc[mt][nt], ah[mt], bh[nt]);
                    mma_bf16(acc[mt][nt], ah[mt], bl[nt]);
                    mma_bf16(acc[mt][nt], al[mt], bh[nt]);
                }
        }
        __syncthreads();
    }

    // epilogue: bias (+ optional elu+1)
    #pragma unroll
    for (int mt = 0; mt < 4; mt++) {
        int row = m0 + warpM + mt * 16 + g;
        #pragma unroll
        for (int nt = 0; nt < 4; nt++) {
            int col = n0 + warpN + nt * 8 + 2 * tg;
            float b0 = bias[col], b1 = bias[col + 1];
            float v0 = acc[mt][nt][0] + b0;
            float v1 = acc[mt][nt][1] + b1;
            float v2 = acc[mt][nt][2] + b0;
            float v3 = acc[mt][nt][3] + b1;
            if (act) {
                v0 = (v0 > 0.f) ? (v0 + 1.f) : expf(v0);
                v1 = (v1 > 0.f) ? (v1 + 1.f) : expf(v1);
                v2 = (v2 > 0.f) ? (v2 + 1.f) : expf(v2);
                v3 = (v3 > 0.f) ? (v3 + 1.f) : expf(v3);
            }
            *(float2*)&C[(size_t)row * EE + col]       = make_float2(v0, v1);
            *(float2*)&C[(size_t)(row + 8) * EE + col] = make_float2(v2, v3);
        }
    }
}

// grid (8, 128, 3): z selects Q/K/V
__global__ void __launch_bounds__(GT)
qkv_mma_kernel(const float* __restrict__ bq,
               const float* __restrict__ bk,
               const float* __restrict__ bv)
{
    int z = blockIdx.z;
    const float* b = (z == 0) ? bq : (z == 1) ? bk : bv;
    float* C = (z == 0) ? g_phiQ : (z == 1) ? g_phiK : g_V;
    mma_gemm(g_Xhi, g_Xlo, g_Whi[z], g_Wlo[z], b, C, z < 2 ? 1 : 0);
}

__global__ void __launch_bounds__(GT)
out_mma_kernel(const float* __restrict__ bo, float* __restrict__ out)
{
    mma_gemm(g_Chi, g_Clo, g_Whi[3], g_Wlo[3], bo, out, 0);
}

// ---------------- KV state: S = phiK^T V, Z = sum phiK (split over L) ------
__global__ void __launch_bounds__(256)
kv_state_kernel()
{
    const int bh = blockIdx.x;
    const int p  = blockIdx.y;
    const int b  = bh / HH, h = bh % HH;
    const int lbase = p * (LL / LSPLIT);

    const float* Kp = g_phiK + (size_t)b * LL * EE + h * DD;
    const float* Vp = g_V    + (size_t)b * LL * EE + h * DD;

    __shared__ float Ks[32][64];
    __shared__ float Vs[32][64];

    const int tid = threadIdx.x;
    const int tx = tid & 15, ty = tid >> 4;

    float acc[4][4];
    #pragma unroll
    for (int i = 0; i < 4; i++)
        #pragma unroll
        for (int j = 0; j < 4; j++) acc[i][j] = 0.f;
    float zacc[4] = {0.f, 0.f, 0.f, 0.f};

    for (int l0 = 0; l0 < LL / LSPLIT; l0 += 32) {
        #pragma unroll
        for (int t = 0; t < 2; t++) {
            int f   = tid + 256 * t;
            int row = f >> 4;
            int cg  = f & 15;
            size_t gidx = (size_t)(lbase + l0 + row) * EE + cg * 4;
            *(float4*)&Ks[row][cg * 4] = *(const float4*)&Kp[gidx];
            *(float4*)&Vs[row][cg * 4] = *(const float4*)&Vp[gidx];
        }
        __syncthreads();
        #pragma unroll
        for (int ll = 0; ll < 32; ll++) {
            float rk[4], rv[4];
            *(float4*)rk = *(const float4*)&Ks[ll][ty * 4];
            *(float4*)rv = *(const float4*)&Vs[ll][tx * 4];
            #pragma unroll
            for (int i = 0; i < 4; i++)
                #pragma unroll
                for (int j = 0; j < 4; j++)
                    acc[i][j] += rk[i] * rv[j];
            if (tx == 0) {
                #pragma unroll
                for (int i = 0; i < 4; i++) zacc[i] += rk[i];
            }
        }
        __syncthreads();
    }

    float* Sp = g_Spart + ((size_t)p * BH + bh) * DD * DD;
    #pragma unroll
    for (int i = 0; i < 4; i++)
        #pragma unroll
        for (int j = 0; j < 4; j++)
            Sp[(ty * 4 + i) * DD + tx * 4 + j] = acc[i][j];
    if (tx == 0) {
        float* Zp = g_Zpart + ((size_t)p * BH + bh) * DD;
        #pragma unroll
        for (int i = 0; i < 4; i++) Zp[ty * 4 + i] = zacc[i];
    }
}

__global__ void __launch_bounds__(256)
reduce_kernel()
{
    int idx = blockIdx.x * 256 + threadIdx.x;
    if (idx < BH * DD * DD) {
        float s = 0.f;
        #pragma unroll
        for (int pp = 0; pp < LSPLIT; pp++) s += g_Spart[(size_t)pp * BH * DD * DD + idx];
        g_S[idx] = s;
    }
    if (idx < BH * DD) {
        float s = 0.f;
        #pragma unroll
        for (int pp = 0; pp < LSPLIT; pp++) s += g_Zpart[(size_t)pp * BH * DD + idx];
        g_Z[idx] = s;
    }
}

// ---------------- context = (phiQ @ S) / (phiQ . Z + eps) --------------------
// writes ctx directly as bf16 hi/lo planes for the out-projection GEMM.
__global__ void __launch_bounds__(256)
attn_out_kernel()
{
    __shared__ float Ss[DD][68];
    __shared__ float Qt[DD][68];   // Qt[k][l] (transposed)
    __shared__ float Zs[DD];

    const int bh = blockIdx.x;
    const int b  = bh >> 4, h = bh & 15;
    const int l0 = blockIdx.y * 64;
    const int tid = threadIdx.x;

    const float* Sp = g_S + (size_t)bh * DD * DD;
    const float* Qp = g_phiQ + (size_t)b * LL * EE + h * DD;

    for (int idx = tid; idx < DD * DD; idx += 256) {
        int r = idx >> 6, c = idx & 63;
        Ss[r][c] = Sp[idx];
        Qt[c][r] = Qp[(size_t)(l0 + r) * EE + c];
    }
    if (tid < DD) Zs[tid] = g_Z[bh * DD + tid];
    __syncthreads();

    const int tx = tid & 15, ty = tid >> 4;
    float num[4][4];
    float den[4] = {0.f, 0.f, 0.f, 0.f};
    #pragma unroll
    for (int i = 0; i < 4; i++)
        #pragma unroll
        for (int j = 0; j < 4; j++) num[i][j] = 0.f;

    #pragma unroll 8
    for (int k = 0; k < DD; k++) {
        float4 q = *(const float4*)&Qt[k][ty * 4];
        float4 s = *(const float4*)&Ss[k][tx * 4];
        float  z = Zs[k];
        float qa[4] = {q.x, q.y, q.z, q.w};
        float sa[4] = {s.x, s.y, s.z, s.w};
        #pragma unroll
        for (int i = 0; i < 4; i++) {
            #pragma unroll
            for (int j = 0; j < 4; j++) num[i][j] += qa[i] * sa[j];
            den[i] += qa[i] * z;
        }
    }

    #pragma unroll
    for (int i = 0; i < 4; i++) {
        float inv = 1.f / (den[i] + 1e-6f);
        uint32_t hp[2], lp[2];
        #pragma unroll
        for (int p = 0; p < 2; p++) {
            float x0 = num[i][2*p]   * inv;
            float x1 = num[i][2*p+1] * inv;
            __nv_bfloat16 h0 = __float2bfloat16(x0);
            __nv_bfloat16 h1 = __float2bfloat16(x1);
            __nv_bfloat16 l0v = __float2bfloat16(x0 - __bfloat162float(h0));
            __nv_bfloat16 l1v = __float2bfloat16(x1 - __bfloat162float(h1));
            hp[p] = ((uint32_t)__bfloat16_as_ushort(h1) << 16) | __bfloat16_as_ushort(h0);
            lp[p] = ((uint32_t)__bfloat16_as_ushort(l1v) << 16) | __bfloat16_as_ushort(l0v);
        }
        size_t idx = (size_t)(b * LL + l0 + ty * 4 + i) * EE + h * DD + tx * 4;
        *(uint2*)(g_Chi + idx) = make_uint2(hp[0], hp[1]);
        *(uint2*)(g_Clo + idx) = make_uint2(lp[0], lp[1]);
    }
}

// ---------------------------------------------------------------------------
extern "C" void kernel_launch(void* const* d_in, const int* in_sizes, int n_in,
                              void* d_out, int out_size)
{
    const float* X  = (const float*)d_in[0];
    const float* Wq = (const float*)d_in[1];
    const float* bq = (const float*)d_in[2];
    const float* Wk = (const float*)d_in[3];
    const float* bk = (const float*)d_in[4];
    const float* Wv = (const float*)d_in[5];
    const float* bv = (const float*)d_in[6];
    const float* Wo = (const float*)d_in[7];
    const float* bo = (const float*)d_in[8];
    float* out = (float*)d_out;

    cudaFuncSetAttribute(qkv_mma_kernel, cudaFuncAttributeMaxDynamicSharedMemorySize, SMEM_BYTES);
    cudaFuncSetAttribute(out_mma_kernel, cudaFuncAttributeMaxDynamicSharedMemorySize, SMEM_BYTES);

    // split X and weights into bf16 hi/lo planes
    split_kernel<<<(MM * EE) / 1024, 256>>>(X,  0, MM * EE);
    split_kernel<<<(EE * EE) / 1024, 256>>>(Wq, 1, EE * EE);
    split_kernel<<<(EE * EE) / 1024, 256>>>(Wk, 2, EE * EE);
    split_kernel<<<(EE * EE) / 1024, 256>>>(Wv, 3, EE * EE);
    split_kernel<<<(EE * EE) / 1024, 256>>>(Wo, 4, EE * EE);

    dim3 gqkv(EE / BN, MM / BM, 3);
    qkv_mma_kernel<<<gqkv, GT, SMEM_BYTES>>>(bq, bk, bv);

    kv_state_kernel<<<dim3(BH, LSPLIT), 256>>>();
    reduce_kernel<<<(BH * DD * DD + 255) / 256, 256>>>();
    attn_out_kernel<<<dim3(BH, LL / 64), 256>>>();

    dim3 gout(EE / BN, MM / BM, 1);
    out_mma_kernel<<<gout, GT, SMEM_BYTES>>>(bo, out);
}

// round 11
// speedup vs baseline: 2.6735x; 1.0544x over previous
#include <cuda_runtime.h>
#include <cuda_bf16.h>
#include <cstdint>
#include <math.h>

// Problem dims (fixed by the reference)
#define BB 4
#define LL 4096
#define EE 1024
#define HH 16
#define DD 64
#define BH (BB*HH)       // 64
#define MM (BB*LL)       // 16384
#define LSPLIT 8

// GEMM tiling (bf16 split mma.sync)
#define BM 128
#define BN 128
#define BK 32                         // fp32-equivalent K per stage
#define PITCH 20                      // u32 per smem row (80B): conflict-free + 16B aligned
#define PLANE_U32 (128*PITCH)         // one operand plane (hi or lo): 10240 B
#define STAGE_U32 (4*PLANE_U32)       // Ahi,Alo,Bhi,Blo
#define SMEM_BYTES (2*STAGE_U32*4)    // double buffered = 81920 B
#define GT 256

// ---------------- scratch ---------------------------------------------------
__device__ __nv_bfloat16 g_Xhi[MM*EE], g_Xlo[MM*EE];
__device__ __nv_bfloat16 g_Whi[4][EE*EE], g_Wlo[4][EE*EE];   // q,k,v,o
__device__ __nv_bfloat16 g_Chi[MM*EE], g_Clo[MM*EE];         // ctx split
__device__ float g_phiQ[MM*EE];
__device__ float g_phiK[MM*EE];
__device__ float g_V  [MM*EE];
__device__ float g_S  [BH*DD*DD];
__device__ float g_Z  [BH*DD];
__device__ float g_Spart[LSPLIT*BH*DD*DD];
__device__ float g_Zpart[LSPLIT*BH*DD];

// ---------------- helpers ---------------------------------------------------
__device__ __forceinline__ void cpasync16(uint32_t dst, const void* src){
    asm volatile("cp.async.cg.shared.global [%0], [%1], 16;" :: "r"(dst), "l"(src) : "memory");
}
__device__ __forceinline__ void cp_commit(){
    asm volatile("cp.async.commit_group;" ::: "memory");
}
template<int N> __device__ __forceinline__ void cp_wait(){
    asm volatile("cp.async.wait_group %0;" :: "n"(N) : "memory");
}
__device__ __forceinline__ uint32_t smem_u32(const void* p){
    uint32_t a;
    asm("{ .reg .u64 t; cvta.to.shared.u64 t, %1; cvt.u32.u64 %0, t; }" : "=r"(a) : "l"(p));
    return a;
}
__device__ __forceinline__ void mma_bf16(float* c, const uint32_t* a, const uint32_t* b){
    asm volatile("mma.sync.aligned.m16n8k16.row.col.f32.bf16.bf16.f32 "
        "{%0,%1,%2,%3}, {%4,%5,%6,%7}, {%8,%9}, {%0,%1,%2,%3};"
        : "+f"(c[0]), "+f"(c[1]), "+f"(c[2]), "+f"(c[3])
        : "r"(a[0]), "r"(a[1]), "r"(a[2]), "r"(a[3]), "r"(b[0]), "r"(b[1]));
}
__device__ __forceinline__ void ldsm_x4(uint32_t* r, uint32_t addr){
    asm volatile("ldmatrix.sync.aligned.m8n8.x4.shared.b16 {%0,%1,%2,%3}, [%4];"
        : "=r"(r[0]), "=r"(r[1]), "=r"(r[2]), "=r"(r[3]) : "r"(addr));
}

// ---------------- fp32 -> bf16 hi/lo split pre-pass -------------------------
// which: 0 = X, 1..4 = Wq,Wk,Wv,Wo
__global__ void __launch_bounds__(256)
split_kernel(const float* __restrict__ src, int which, int n)
{
    __nv_bfloat16* hi;
    __nv_bfloat16* lo;
    if (which == 0)      { hi = g_Xhi;     lo = g_Xlo;     }
    else                 { hi = g_Whi[which-1]; lo = g_Wlo[which-1]; }

    int i = (blockIdx.x * 256 + threadIdx.x) * 4;
    if (i >= n) return;
    float4 v = *(const float4*)(src + i);
    float x[4] = {v.x, v.y, v.z, v.w};
    uint32_t hp[2], lp[2];
    #pragma unroll
    for (int p = 0; p < 2; p++) {
        __nv_bfloat16 h0 = __float2bfloat16(x[2*p]);
        __nv_bfloat16 h1 = __float2bfloat16(x[2*p+1]);
        __nv_bfloat16 l0 = __float2bfloat16(x[2*p]   - __bfloat162float(h0));
        __nv_bfloat16 l1 = __float2bfloat16(x[2*p+1] - __bfloat162float(h1));
        hp[p] = ((uint32_t)__bfloat16_as_ushort(h1) << 16) | __bfloat16_as_ushort(h0);
        lp[p] = ((uint32_t)__bfloat16_as_ushort(l1) << 16) | __bfloat16_as_ushort(l0);
    }
    *(uint2*)(hi + i) = make_uint2(hp[0], hp[1]);
    *(uint2*)(lo + i) = make_uint2(lp[0], lp[1]);
}

// ---------------- bf16-split tensor-core GEMM body --------------------------
// C[m,n] = sum_k A[m,k]*W[n,k] + bias[n] via hi*hi + hi*lo + lo*hi.
__device__ __forceinline__ void load_tile(uint32_t st,
                                          const __nv_bfloat16* __restrict__ Ahi,
                                          const __nv_bfloat16* __restrict__ Alo,
                                          const __nv_bfloat16* __restrict__ Bhi,
                                          const __nv_bfloat16* __restrict__ Blo,
                                          int m0, int n0, int k0, int tid)
{
    #pragma unroll
    for (int t = 0; t < 2; t++) {
        int p   = tid + GT * t;          // 0..511
        int row = p >> 2;                // 0..127
        int cg  = p & 3;                 // 16B chunk within 64B row (32 bf16)
        uint32_t off = (uint32_t)(row * PITCH * 4 + cg * 16);
        size_t ga = (size_t)(m0 + row) * EE + k0 + cg * 8;
        size_t gb = (size_t)(n0 + row) * EE + k0 + cg * 8;
        cpasync16(st + off,                    Ahi + ga);
        cpasync16(st + PLANE_U32*4   + off,    Alo + ga);
        cpasync16(st + 2*PLANE_U32*4 + off,    Bhi + gb);
        cpasync16(st + 3*PLANE_U32*4 + off,    Blo + gb);
    }
}

__device__ __forceinline__ void mma_gemm(const __nv_bfloat16* __restrict__ Ahi,
                                         const __nv_bfloat16* __restrict__ Alo,
                                         const __nv_bfloat16* __restrict__ Bhi,
                                         const __nv_bfloat16* __restrict__ Blo,
                                         const float* __restrict__ bias,
                                         float* __restrict__ C, int act)
{
    extern __shared__ uint32_t smem[];
    const uint32_t sbase = smem_u32(smem);

    const int tid  = threadIdx.x;
    const int wid  = tid >> 5;
    const int lane = tid & 31;
    const int g    = lane >> 2;          // row within 8
    const int tg   = lane & 3;           // thread-in-group
    const int m0   = blockIdx.y * BM;
    const int n0   = blockIdx.x * BN;
    const int warpM = (wid >> 2) * 64;   // 2 warps in M
    const int warpN = (wid & 3) * 32;    // 4 warps in N

    // ldmatrix lane addressing (precomputed, loop-invariant)
    const int a_row = lane & 15;               // A: lanes 0-15 rows, 16-31 k-half
    const int a_col = (lane >> 4) * 16;        // byte offset for k half
    const int b_row = lane & 7;                // B: row within 8-wide n tile
    const int b_sel = ((lane >> 3) & 1) * 16;  // k-half byte offset
    const int b_pair = (lane >> 4);            // which nt of the pair

    float acc[4][4][4];
    #pragma unroll
    for (int i = 0; i < 4; i++)
        #pragma unroll
        for (int j = 0; j < 4; j++)
            #pragma unroll
            for (int r = 0; r < 4; r++) acc[i][j][r] = 0.f;

    load_tile(sbase, Ahi, Alo, Bhi, Blo, m0, n0, 0, tid);
    cp_commit();

    const int NIT = EE / BK;             // 32
    for (int it = 0; it < NIT; it++) {
        if (it + 1 < NIT) {
            load_tile(sbase + ((it + 1) & 1) * STAGE_U32 * 4,
                      Ahi, Alo, Bhi, Blo, m0, n0, (it + 1) * BK, tid);
            cp_commit();
            cp_wait<1>();
        } else {
            cp_wait<0>();
        }
        __syncthreads();

        const uint32_t stage = sbase + (it & 1) * STAGE_U32 * 4;
        const uint32_t A_hi = stage;
        const uint32_t A_lo = stage + PLANE_U32 * 4;
        const uint32_t B_hi = stage + 2 * PLANE_U32 * 4;
        const uint32_t B_lo = stage + 3 * PLANE_U32 * 4;

        #pragma unroll
        for (int kb = 0; kb < 2; kb++) {         // two k16 blocks per BK=32
            const uint32_t kbyte = kb * 32;      // 16 bf16 = 32 bytes
            uint32_t ah[4][4], al[4][4], bh[4][2], bl[4][2];

            #pragma unroll
            for (int mt = 0; mt < 4; mt++) {
                uint32_t aoff = (uint32_t)(warpM + mt * 16 + a_row) * (PITCH * 4)
                                + kbyte + a_col;
                ldsm_x4(ah[mt], A_hi + aoff);
                ldsm_x4(al[mt], A_lo + aoff);
            }
            #pragma unroll
            for (int p = 0; p < 2; p++) {        // nt pairs (0,1) and (2,3)
                uint32_t boff = (uint32_t)(warpN + (2 * p + b_pair) * 8 + b_row) * (PITCH * 4)
                                + kbyte + b_sel;
                uint32_t th[4], tl[4];
                ldsm_x4(th, B_hi + boff);
                ldsm_x4(tl, B_lo + boff);
                bh[2*p][0] = th[0]; bh[2*p][1] = th[1];
                bh[2*p+1][0] = th[2]; bh[2*p+1][1] = th[3];
                bl[2*p][0] = tl[0]; bl[2*p][1] = tl[1];
                bl[2*p+1][0] = tl[2]; bl[2*p+1][1] = tl[3];
            }

            #pragma unroll
            for (int mt = 0; mt < 4; mt++)
                #pragma unroll
                for (int nt = 0; nt < 4; nt++) {
                    mma_bf16(acc[mt][nt], ah[mt], bh[nt]);
                    mma_bf16(acc[mt][nt], ah[mt], bl[nt]);
                    mma_bf16(acc[mt][nt], al[mt], bh[nt]);
                }
        }
        __syncthreads();
    }

    // epilogue: bias (+ optional elu+1)
    #pragma unroll
    for (int mt = 0; mt < 4; mt++) {
        int row = m0 + warpM + mt * 16 + g;
        #pragma unroll
        for (int nt = 0; nt < 4; nt++) {
            int col = n0 + warpN + nt * 8 + 2 * tg;
            float b0 = bias[col], b1 = bias[col + 1];
            float v0 = acc[mt][nt][0] + b0;
            float v1 = acc[mt][nt][1] + b1;
            float v2 = acc[mt][nt][2] + b0;
            float v3 = acc[mt][nt][3] + b1;
            if (act) {
                v0 = (v0 > 0.f) ? (v0 + 1.f) : expf(v0);
                v1 = (v1 > 0.f) ? (v1 + 1.f) : expf(v1);
                v2 = (v2 > 0.f) ? (v2 + 1.f) : expf(v2);
                v3 = (v3 > 0.f) ? (v3 + 1.f) : expf(v3);
            }
            *(float2*)&C[(size_t)row * EE + col]       = make_float2(v0, v1);
            *(float2*)&C[(size_t)(row + 8) * EE + col] = make_float2(v2, v3);
        }
    }
}

// grid (8, 128, 3): z selects Q/K/V
__global__ void __launch_bounds__(GT)
qkv_mma_kernel(const float* __restrict__ bq,
               const float* __restrict__ bk,
               const float* __restrict__ bv)
{
    int z = blockIdx.z;
    const float* b = (z == 0) ? bq : (z == 1) ? bk : bv;
    float* C = (z == 0) ? g_phiQ : (z == 1) ? g_phiK : g_V;
    mma_gemm(g_Xhi, g_Xlo, g_Whi[z], g_Wlo[z], b, C, z < 2 ? 1 : 0);
}

__global__ void __launch_bounds__(GT)
out_mma_kernel(const float* __restrict__ bo, float* __restrict__ out)
{
    mma_gemm(g_Chi, g_Clo, g_Whi[3], g_Wlo[3], bo, out, 0);
}

// ---------------- KV state: S = phiK^T V, Z = sum phiK (split over L) ------
__global__ void __launch_bounds__(256)
kv_state_kernel()
{
    const int bh = blockIdx.x;
    const int p  = blockIdx.y;
    const int b  = bh / HH, h = bh % HH;
    const int lbase = p * (LL / LSPLIT);

    const float* Kp = g_phiK + (size_t)b * LL * EE + h * DD;
    const float* Vp = g_V    + (size_t)b * LL * EE + h * DD;

    __shared__ float Ks[32][64];
    __shared__ float Vs[32][64];

    const int tid = threadIdx.x;
    const int tx = tid & 15, ty = tid >> 4;

    float acc[4][4];
    #pragma unroll
    for (int i = 0; i < 4; i++)
        #pragma unroll
        for (int j = 0; j < 4; j++) acc[i][j] = 0.f;
    float zacc[4] = {0.f, 0.f, 0.f, 0.f};

    for (int l0 = 0; l0 < LL / LSPLIT; l0 += 32) {
        #pragma unroll
        for (int t = 0; t < 2; t++) {
            int f   = tid + 256 * t;
            int row = f >> 4;
            int cg  = f & 15;
            size_t gidx = (size_t)(lbase + l0 + row) * EE + cg * 4;
            *(float4*)&Ks[row][cg * 4] = *(const float4*)&Kp[gidx];
            *(float4*)&Vs[row][cg * 4] = *(const float4*)&Vp[gidx];
        }
        __syncthreads();
        #pragma unroll
        for (int ll = 0; ll < 32; ll++) {
            float rk[4], rv[4];
            *(float4*)rk = *(const float4*)&Ks[ll][ty * 4];
            *(float4*)rv = *(const float4*)&Vs[ll][tx * 4];
            #pragma unroll
            for (int i = 0; i < 4; i++)
                #pragma unroll
                for (int j = 0; j < 4; j++)
                    acc[i][j] += rk[i] * rv[j];
            if (tx == 0) {
                #pragma unroll
                for (int i = 0; i < 4; i++) zacc[i] += rk[i];
            }
        }
        __syncthreads();
    }

    float* Sp = g_Spart + ((size_t)p * BH + bh) * DD * DD;
    #pragma unroll
    for (int i = 0; i < 4; i++)
        #pragma unroll
        for (int j = 0; j < 4; j++)
            Sp[(ty * 4 + i) * DD + tx * 4 + j] = acc[i][j];
    if (tx == 0) {
        float* Zp = g_Zpart + ((size_t)p * BH + bh) * DD;
        #pragma unroll
        for (int i = 0; i < 4; i++) Zp[ty * 4 + i] = zacc[i];
    }
}

__global__ void __launch_bounds__(256)
reduce_kernel()
{
    int idx = blockIdx.x * 256 + threadIdx.x;
    if (idx < BH * DD * DD) {
        float s = 0.f;
        #pragma unroll
        for (int pp = 0; pp < LSPLIT; pp++) s += g_Spart[(size_t)pp * BH * DD * DD + idx];
        g_S[idx] = s;
    }
    if (idx < BH * DD) {
        float s = 0.f;
        #pragma unroll
        for (int pp = 0; pp < LSPLIT; pp++) s += g_Zpart[(size_t)pp * BH * DD + idx];
        g_Z[idx] = s;
    }
}

// ---------------- context = (phiQ @ S) / (phiQ . Z + eps) --------------------
// writes ctx directly as bf16 hi/lo planes for the out-projection GEMM.
__global__ void __launch_bounds__(256)
attn_out_kernel()
{
    __shared__ float Ss[DD][68];
    __shared__ float Qt[DD][68];   // Qt[k][l] (transposed)
    __shared__ float Zs[DD];

    const int bh = blockIdx.x;
    const int b  = bh >> 4, h = bh & 15;
    const int l0 = blockIdx.y * 64;
    const int tid = threadIdx.x;

    const float* Sp = g_S + (size_t)bh * DD * DD;
    const float* Qp = g_phiQ + (size_t)b * LL * EE + h * DD;

    for (int idx = tid; idx < DD * DD; idx += 256) {
        int r = idx >> 6, c = idx & 63;
        Ss[r][c] = Sp[idx];
        Qt[c][r] = Qp[(size_t)(l0 + r) * EE + c];
    }
    if (tid < DD) Zs[tid] = g_Z[bh * DD + tid];
    __syncthreads();

    const int tx = tid & 15, ty = tid >> 4;
    float num[4][4];
    float den[4] = {0.f, 0.f, 0.f, 0.f};
    #pragma unroll
    for (int i = 0; i < 4; i++)
        #pragma unroll
        for (int j = 0; j < 4; j++) num[i][j] = 0.f;

    #pragma unroll 8
    for (int k = 0; k < DD; k++) {
        float4 q = *(const float4*)&Qt[k][ty * 4];
        float4 s = *(const float4*)&Ss[k][tx * 4];
        float  z = Zs[k];
        float qa[4] = {q.x, q.y, q.z, q.w};
        float sa[4] = {s.x, s.y, s.z, s.w};
        #pragma unroll
        for (int i = 0; i < 4; i++) {
            #pragma unroll
            for (int j = 0; j < 4; j++) num[i][j] += qa[i] * sa[j];
            den[i] += qa[i] * z;
        }
    }

    #pragma unroll
    for (int i = 0; i < 4; i++) {
        float inv = 1.f / (den[i] + 1e-6f);
        uint32_t hp[2], lp[2];
        #pragma unroll
        for (int p = 0; p < 2; p++) {
            float x0 = num[i][2*p]   * inv;
            float x1 = num[i][2*p+1] * inv;
            __nv_bfloat16 h0 = __float2bfloat16(x0);
            __nv_bfloat16 h1 = __float2bfloat16(x1);
            __nv_bfloat16 l0v = __float2bfloat16(x0 - __bfloat162float(h0));
            __nv_bfloat16 l1v = __float2bfloat16(x1 - __bfloat162float(h1));
            hp[p] = ((uint32_t)__bfloat16_as_ushort(h1) << 16) | __bfloat16_as_ushort(h0);
            lp[p] = ((uint32_t)__bfloat16_as_ushort(l1v) << 16) | __bfloat16_as_ushort(l0v);
        }
        size_t idx = (size_t)(b * LL + l0 + ty * 4 + i) * EE + h * DD + tx * 4;
        *(uint2*)(g_Chi + idx) = make_uint2(hp[0], hp[1]);
        *(uint2*)(g_Clo + idx) = make_uint2(lp[0], lp[1]);
    }
}

// ---------------------------------------------------------------------------
extern "C" void kernel_launch(void* const* d_in, const int* in_sizes, int n_in,
                              void* d_out, int out_size)
{
    const float* X  = (const float*)d_in[0];
    const float* Wq = (const float*)d_in[1];
    const float* bq = (const float*)d_in[2];
    const float* Wk = (const float*)d_in[3];
    const float* bk = (const float*)d_in[4];
    const float* Wv = (const float*)d_in[5];
    const float* bv = (const float*)d_in[6];
    const float* Wo = (const float*)d_in[7];
    const float* bo = (const float*)d_in[8];
    float* out = (float*)d_out;

    cudaFuncSetAttribute(qkv_mma_kernel, cudaFuncAttributeMaxDynamicSharedMemorySize, SMEM_BYTES);
    cudaFuncSetAttribute(out_mma_kernel, cudaFuncAttributeMaxDynamicSharedMemorySize, SMEM_BYTES);

    // split X and weights into bf16 hi/lo planes
    split_kernel<<<(MM * EE) / 1024, 256>>>(X,  0, MM * EE);
    split_kernel<<<(EE * EE) / 1024, 256>>>(Wq, 1, EE * EE);
    split_kernel<<<(EE * EE) / 1024, 256>>>(Wk, 2, EE * EE);
    split_kernel<<<(EE * EE) / 1024, 256>>>(Wv, 3, EE * EE);
    split_kernel<<<(EE * EE) / 1024, 256>>>(Wo, 4, EE * EE);

    dim3 gqkv(EE / BN, MM / BM, 3);
    qkv_mma_kernel<<<gqkv, GT, SMEM_BYTES>>>(bq, bk, bv);

    kv_state_kernel<<<dim3(BH, LSPLIT), 256>>>();
    reduce_kernel<<<(BH * DD * DD + 255) / 256, 256>>>();
    attn_out_kernel<<<dim3(BH, LL / 64), 256>>>();

    dim3 gout(EE / BN, MM / BM, 1);
    out_mma_kernel<<<gout, GT, SMEM_BYTES>>>(bo, out);
}

// round 12
// speedup vs baseline: 2.6946x; 1.0079x over previous
#include <cuda_runtime.h>
#include <cuda_bf16.h>
#include <cstdint>
#include <math.h>

// Problem dims (fixed by the reference)
#define BB 4
#define LL 4096
#define EE 1024
#define HH 16
#define DD 64
#define BH (BB*HH)       // 64
#define MM (BB*LL)       // 16384
#define LSPLIT 8

// GEMM tiling (bf16 split mma.sync)
#define BM 128
#define BN 128
#define BK 32                         // fp32-equivalent K per stage
#define PITCH 20                      // u32 per smem row (80B): conflict-free + 16B aligned
#define PLANE_U32 (128*PITCH)         // one operand plane (hi or lo): 10240 B
#define STAGE_U32 (4*PLANE_U32)       // Ahi,Alo,Bhi,Blo
#define SMEM_BYTES (2*STAGE_U32*4)    // double buffered = 81920 B
#define GT 256

// kv_state MMA tiling
#define KPITCH 40                     // bf16 per smem row (80B) — same bank rotation
#define KPB 80                        // bytes per row
#define KPLANE (64*KPITCH)            // bf16 units per plane
#define KV_LC (LL/LSPLIT)             // 512 l per split
#define KV_NST (KV_LC/32)             // 16 stages

// ---------------- scratch ---------------------------------------------------
__device__ __nv_bfloat16 g_Xhi[MM*EE], g_Xlo[MM*EE];
__device__ __nv_bfloat16 g_Whi[4][EE*EE], g_Wlo[4][EE*EE];   // q,k,v,o
__device__ __nv_bfloat16 g_Chi[MM*EE], g_Clo[MM*EE];         // ctx split
__device__ __nv_bfloat16 g_KThi[BH*DD*LL], g_KTlo[BH*DD*LL]; // phiK transposed [bh][d][l]
__device__ __nv_bfloat16 g_VThi[BH*DD*LL], g_VTlo[BH*DD*LL]; // V transposed
__device__ float g_phiQ[MM*EE];
__device__ float g_S  [BH*DD*DD];
__device__ float g_Z  [BH*DD];
__device__ float g_Spart[LSPLIT*BH*DD*DD];
__device__ float g_Zpart[LSPLIT*BH*DD];

// ---------------- helpers ---------------------------------------------------
__device__ __forceinline__ void cpasync16(uint32_t dst, const void* src){
    asm volatile("cp.async.cg.shared.global [%0], [%1], 16;" :: "r"(dst), "l"(src) : "memory");
}
__device__ __forceinline__ void cp_commit(){
    asm volatile("cp.async.commit_group;" ::: "memory");
}
template<int N> __device__ __forceinline__ void cp_wait(){
    asm volatile("cp.async.wait_group %0;" :: "n"(N) : "memory");
}
__device__ __forceinline__ uint32_t smem_u32(const void* p){
    uint32_t a;
    asm("{ .reg .u64 t; cvta.to.shared.u64 t, %1; cvt.u32.u64 %0, t; }" : "=r"(a) : "l"(p));
    return a;
}
__device__ __forceinline__ void mma_bf16(float* c, const uint32_t* a, const uint32_t* b){
    asm volatile("mma.sync.aligned.m16n8k16.row.col.f32.bf16.bf16.f32 "
        "{%0,%1,%2,%3}, {%4,%5,%6,%7}, {%8,%9}, {%0,%1,%2,%3};"
        : "+f"(c[0]), "+f"(c[1]), "+f"(c[2]), "+f"(c[3])
        : "r"(a[0]), "r"(a[1]), "r"(a[2]), "r"(a[3]), "r"(b[0]), "r"(b[1]));
}
__device__ __forceinline__ void ldsm_x4(uint32_t* r, uint32_t addr){
    asm volatile("ldmatrix.sync.aligned.m8n8.x4.shared.b16 {%0,%1,%2,%3}, [%4];"
        : "=r"(r[0]), "=r"(r[1]), "=r"(r[2]), "=r"(r[3]) : "r"(addr));
}
__device__ __forceinline__ void bsplit(float x, __nv_bfloat16& h, __nv_bfloat16& l){
    h = __float2bfloat16(x);
    l = __float2bfloat16(x - __bfloat162float(h));
}

// ---------------- fp32 -> bf16 hi/lo split pre-pass -------------------------
// which: 0 = X, 1..4 = Wq,Wk,Wv,Wo
__global__ void __launch_bounds__(256)
split_kernel(const float* __restrict__ src, int which, int n)
{
    __nv_bfloat16* hi;
    __nv_bfloat16* lo;
    if (which == 0)      { hi = g_Xhi;     lo = g_Xlo;     }
    else                 { hi = g_Whi[which-1]; lo = g_Wlo[which-1]; }

    int i = (blockIdx.x * 256 + threadIdx.x) * 4;
    if (i >= n) return;
    float4 v = *(const float4*)(src + i);
    float x[4] = {v.x, v.y, v.z, v.w};
    uint32_t hp[2], lp[2];
    #pragma unroll
    for (int p = 0; p < 2; p++) {
        __nv_bfloat16 h0, l0, h1, l1;
        bsplit(x[2*p],   h0, l0);
        bsplit(x[2*p+1], h1, l1);
        hp[p] = ((uint32_t)__bfloat16_as_ushort(h1) << 16) | __bfloat16_as_ushort(h0);
        lp[p] = ((uint32_t)__bfloat16_as_ushort(l1) << 16) | __bfloat16_as_ushort(l0);
    }
    *(uint2*)(hi + i) = make_uint2(hp[0], hp[1]);
    *(uint2*)(lo + i) = make_uint2(lp[0], lp[1]);
}

// ---------------- bf16-split tensor-core GEMM body --------------------------
// mode 0: fp32 out; 1: elu+1 fp32 out; 2: elu+1 -> transposed hi/lo; 3: plain -> transposed hi/lo
__device__ __forceinline__ void load_tile(uint32_t st,
                                          const __nv_bfloat16* __restrict__ Ahi,
                                          const __nv_bfloat16* __restrict__ Alo,
                                          const __nv_bfloat16* __restrict__ Bhi,
                                          const __nv_bfloat16* __restrict__ Blo,
                                          int m0, int n0, int k0, int tid)
{
    #pragma unroll
    for (int t = 0; t < 2; t++) {
        int p   = tid + GT * t;          // 0..511
        int row = p >> 2;                // 0..127
        int cg  = p & 3;                 // 16B chunk within 64B row (32 bf16)
        uint32_t off = (uint32_t)(row * PITCH * 4 + cg * 16);
        size_t ga = (size_t)(m0 + row) * EE + k0 + cg * 8;
        size_t gb = (size_t)(n0 + row) * EE + k0 + cg * 8;
        cpasync16(st + off,                    Ahi + ga);
        cpasync16(st + PLANE_U32*4   + off,    Alo + ga);
        cpasync16(st + 2*PLANE_U32*4 + off,    Bhi + gb);
        cpasync16(st + 3*PLANE_U32*4 + off,    Blo + gb);
    }
}

__device__ __forceinline__ void mma_gemm(const __nv_bfloat16* __restrict__ Ahi,
                                         const __nv_bfloat16* __restrict__ Alo,
                                         const __nv_bfloat16* __restrict__ Bhi,
                                         const __nv_bfloat16* __restrict__ Blo,
                                         const float* __restrict__ bias,
                                         float* __restrict__ C,
                                         __nv_bfloat16* __restrict__ Thi,
                                         __nv_bfloat16* __restrict__ Tlo,
                                         int mode)
{
    extern __shared__ uint32_t smem[];
    const uint32_t sbase = smem_u32(smem);

    const int tid  = threadIdx.x;
    const int wid  = tid >> 5;
    const int lane = tid & 31;
    const int g    = lane >> 2;
    const int tg   = lane & 3;
    const int m0   = blockIdx.y * BM;
    const int n0   = blockIdx.x * BN;
    const int warpM = (wid >> 2) * 64;
    const int warpN = (wid & 3) * 32;

    const int a_row = lane & 15;
    const int a_col = (lane >> 4) * 16;
    const int b_row = lane & 7;
    const int b_sel = ((lane >> 3) & 1) * 16;
    const int b_pair = (lane >> 4);

    float acc[4][4][4];
    #pragma unroll
    for (int i = 0; i < 4; i++)
        #pragma unroll
        for (int j = 0; j < 4; j++)
            #pragma unroll
            for (int r = 0; r < 4; r++) acc[i][j][r] = 0.f;

    load_tile(sbase, Ahi, Alo, Bhi, Blo, m0, n0, 0, tid);
    cp_commit();

    const int NIT = EE / BK;             // 32
    for (int it = 0; it < NIT; it++) {
        if (it + 1 < NIT) {
            load_tile(sbase + ((it + 1) & 1) * STAGE_U32 * 4,
                      Ahi, Alo, Bhi, Blo, m0, n0, (it + 1) * BK, tid);
            cp_commit();
            cp_wait<1>();
        } else {
            cp_wait<0>();
        }
        __syncthreads();

        const uint32_t stage = sbase + (it & 1) * STAGE_U32 * 4;
        const uint32_t A_hi = stage;
        const uint32_t A_lo = stage + PLANE_U32 * 4;
        const uint32_t B_hi = stage + 2 * PLANE_U32 * 4;
        const uint32_t B_lo = stage + 3 * PLANE_U32 * 4;

        #pragma unroll
        for (int kb = 0; kb < 2; kb++) {
            const uint32_t kbyte = kb * 32;
            uint32_t ah[4][4], al[4][4], bh[4][2], bl[4][2];

            #pragma unroll
            for (int mt = 0; mt < 4; mt++) {
                uint32_t aoff = (uint32_t)(warpM + mt * 16 + a_row) * (PITCH * 4)
                                + kbyte + a_col;
                ldsm_x4(ah[mt], A_hi + aoff);
                ldsm_x4(al[mt], A_lo + aoff);
            }
            #pragma unroll
            for (int p = 0; p < 2; p++) {
                uint32_t boff = (uint32_t)(warpN + (2 * p + b_pair) * 8 + b_row) * (PITCH * 4)
                                + kbyte + b_sel;
                uint32_t th[4], tl[4];
                ldsm_x4(th, B_hi + boff);
                ldsm_x4(tl, B_lo + boff);
                bh[2*p][0] = th[0]; bh[2*p][1] = th[1];
                bh[2*p+1][0] = th[2]; bh[2*p+1][1] = th[3];
                bl[2*p][0] = tl[0]; bl[2*p][1] = tl[1];
                bl[2*p+1][0] = tl[2]; bl[2*p+1][1] = tl[3];
            }

            #pragma unroll
            for (int mt = 0; mt < 4; mt++)
                #pragma unroll
                for (int nt = 0; nt < 4; nt++) {
                    mma_bf16(acc[mt][nt], ah[mt], bh[nt]);
                    mma_bf16(acc[mt][nt], ah[mt], bl[nt]);
                    mma_bf16(acc[mt][nt], al[mt], bh[nt]);
                }
        }
        __syncthreads();   // protect buffer (it&1) from next iteration's cp.async
    }

    // epilogue
    #pragma unroll
    for (int mt = 0; mt < 4; mt++) {
        int row = m0 + warpM + mt * 16 + g;
        #pragma unroll
        for (int nt = 0; nt < 4; nt++) {
            int col = n0 + warpN + nt * 8 + 2 * tg;
            float b0 = bias[col], b1 = bias[col + 1];
            float v0 = acc[mt][nt][0] + b0;
            float v1 = acc[mt][nt][1] + b1;
            float v2 = acc[mt][nt][2] + b0;
            float v3 = acc[mt][nt][3] + b1;
            if (mode == 1 || mode == 2) {
                v0 = (v0 > 0.f) ? (v0 + 1.f) : expf(v0);
                v1 = (v1 > 0.f) ? (v1 + 1.f) : expf(v1);
                v2 = (v2 > 0.f) ? (v2 + 1.f) : expf(v2);
                v3 = (v3 > 0.f) ? (v3 + 1.f) : expf(v3);
            }
            if (mode <= 1) {
                *(float2*)&C[(size_t)row * EE + col]       = make_float2(v0, v1);
                *(float2*)&C[(size_t)(row + 8) * EE + col] = make_float2(v2, v3);
            } else {
                // transposed bf16 hi/lo: dst[(b*1024 + col)][l], l = row % LL
                int bi = row >> 12;
                int l  = row & (LL - 1);
                size_t p0 = ((size_t)(bi * 1024 + col)) * LL + l;
                size_t p1 = p0 + LL;   // col+1
                __nv_bfloat16 h, lo;
                bsplit(v0, h, lo); Thi[p0]     = h; Tlo[p0]     = lo;
                bsplit(v2, h, lo); Thi[p0 + 8] = h; Tlo[p0 + 8] = lo;
                bsplit(v1, h, lo); Thi[p1]     = h; Tlo[p1]     = lo;
                bsplit(v3, h, lo); Thi[p1 + 8] = h; Tlo[p1 + 8] = lo;
            }
        }
    }
}

// grid (8, 128, 3): z selects Q/K/V
__global__ void __launch_bounds__(GT)
qkv_mma_kernel(const float* __restrict__ bq,
               const float* __restrict__ bk,
               const float* __restrict__ bv)
{
    int z = blockIdx.z;
    if (z == 0)
        mma_gemm(g_Xhi, g_Xlo, g_Whi[0], g_Wlo[0], bq, g_phiQ, nullptr, nullptr, 1);
    else if (z == 1)
        mma_gemm(g_Xhi, g_Xlo, g_Whi[1], g_Wlo[1], bk, nullptr, g_KThi, g_KTlo, 2);
    else
        mma_gemm(g_Xhi, g_Xlo, g_Whi[2], g_Wlo[2], bv, nullptr, g_VThi, g_VTlo, 3);
}

__global__ void __launch_bounds__(GT)
out_mma_kernel(const float* __restrict__ bo, float* __restrict__ out)
{
    mma_gemm(g_Chi, g_Clo, g_Whi[3], g_Wlo[3], bo, out, nullptr, nullptr, 0);
}

// ---------------- KV state on tensor cores ----------------------------------
// S_part[bh][i][j] = sum_{l in split} phiK[l,i] * V[l,j], via transposed hi/lo planes.
__global__ void __launch_bounds__(128)
kv_state_mma_kernel()
{
    __shared__ __nv_bfloat16 sm[2][4 * KPLANE];

    const int bh  = blockIdx.x;
    const int p   = blockIdx.y;
    const int tid = threadIdx.x;
    const int wid = tid >> 5;
    const int lane = tid & 31;
    const int g   = lane >> 2;
    const int tg  = lane & 3;
    const int a_row = lane & 15;
    const int a_col = (lane >> 4) * 16;
    const int b_row = lane & 7;
    const int b_sel = ((lane >> 3) & 1) * 16;
    const int b_pair = lane >> 4;

    const size_t gbase = (size_t)bh * DD * LL + (size_t)p * KV_LC;
    const __nv_bfloat16* srcs[4] = { g_KThi + gbase, g_KTlo + gbase,
                                     g_VThi + gbase, g_VTlo + gbase };

    float acc[4][2][4];
    #pragma unroll
    for (int i = 0; i < 4; i++)
        #pragma unroll
        for (int j = 0; j < 2; j++)
            #pragma unroll
            for (int r = 0; r < 4; r++) acc[i][j][r] = 0.f;
    float zacc = 0.f;

    // stage loader: 32 l values for 64 d rows, all four planes
    auto issue_load = [&](int buf, int s){
        uint32_t dst0 = smem_u32(&sm[buf][0]);
        int l0 = s * 32;
        #pragma unroll
        for (int t = 0; t < 8; t++) {
            int q = tid + 128 * t;           // 0..1023
            int plane = q >> 8;
            int rem = q & 255;
            int row = rem >> 2;
            int cg = rem & 3;
            const __nv_bfloat16* src = srcs[plane] + (size_t)row * LL + l0 + cg * 8;
            uint32_t dst = dst0 + (uint32_t)(plane * KPLANE + row * KPITCH + cg * 8) * 2;
            cpasync16(dst, src);
        }
    };

    issue_load(0, 0);
    cp_commit();

    for (int s = 0; s < KV_NST; s++) {
        if (s + 1 < KV_NST) {
            issue_load((s + 1) & 1, s + 1);
            cp_commit();
            cp_wait<1>();
        } else {
            cp_wait<0>();
        }
        __syncthreads();

        uint32_t sb = smem_u32(&sm[s & 1][0]);
        uint32_t Khi = sb;
        uint32_t Klo = sb + KPLANE * 2;
        uint32_t Vhi = sb + 2 * KPLANE * 2;
        uint32_t Vlo = sb + 3 * KPLANE * 2;

        #pragma unroll
        for (int kb = 0; kb < 2; kb++) {
            uint32_t kbyte = kb * 32;
            uint32_t ah[4][4], al[4][4], bhf[2][2], blf[2][2];
            #pragma unroll
            for (int mt = 0; mt < 4; mt++) {
                uint32_t aoff = (uint32_t)(mt * 16 + a_row) * KPB + kbyte + a_col;
                ldsm_x4(ah[mt], Khi + aoff);
                ldsm_x4(al[mt], Klo + aoff);
            }
            uint32_t boff = (uint32_t)(wid * 16 + b_pair * 8 + b_row) * KPB + kbyte + b_sel;
            uint32_t th[4], tl[4];
            ldsm_x4(th, Vhi + boff);
            ldsm_x4(tl, Vlo + boff);
            bhf[0][0] = th[0]; bhf[0][1] = th[1];
            bhf[1][0] = th[2]; bhf[1][1] = th[3];
            blf[0][0] = tl[0]; blf[0][1] = tl[1];
            blf[1][0] = tl[2]; blf[1][1] = tl[3];

            #pragma unroll
            for (int mt = 0; mt < 4; mt++)
                #pragma unroll
                for (int nt = 0; nt < 2; nt++) {
                    mma_bf16(acc[mt][nt], ah[mt], bhf[nt]);
                    mma_bf16(acc[mt][nt], ah[mt], blf[nt]);
                    mma_bf16(acc[mt][nt], al[mt], bhf[nt]);
                }
        }

        // deterministic Z partial: threads 0..63 sum phiK row d over this stage
        if (tid < DD) {
            const __nv_bfloat16* kh = &sm[s & 1][tid * KPITCH];
            const __nv_bfloat16* kl = kh + KPLANE;
            #pragma unroll
            for (int i = 0; i < 32; i++)
                zacc += __bfloat162float(kh[i]) + __bfloat162float(kl[i]);
        }
        __syncthreads();   // protect buffer before next cp.async overwrite
    }

    float* Sp = g_Spart + ((size_t)p * BH + bh) * DD * DD;
    #pragma unroll
    for (int mt = 0; mt < 4; mt++) {
        int m = mt * 16 + g;
        #pragma unroll
        for (int nt = 0; nt < 2; nt++) {
            int n = wid * 16 + nt * 8 + 2 * tg;
            *(float2*)&Sp[m * DD + n]       = make_float2(acc[mt][nt][0], acc[mt][nt][1]);
            *(float2*)&Sp[(m + 8) * DD + n] = make_float2(acc[mt][nt][2], acc[mt][nt][3]);
        }
    }
    if (tid < DD)
        g_Zpart[((size_t)p * BH + bh) * DD + tid] = zacc;
}

__global__ void __launch_bounds__(256)
reduce_kernel()
{
    int idx = blockIdx.x * 256 + threadIdx.x;
    if (idx < BH * DD * DD) {
        float s = 0.f;
        #pragma unroll
        for (int pp = 0; pp < LSPLIT; pp++) s += g_Spart[(size_t)pp * BH * DD * DD + idx];
        g_S[idx] = s;
    }
    if (idx < BH * DD) {
        float s = 0.f;
        #pragma unroll
        for (int pp = 0; pp < LSPLIT; pp++) s += g_Zpart[(size_t)pp * BH * DD + idx];
        g_Z[idx] = s;
    }
}

// ---------------- context = (phiQ @ S) / (phiQ . Z + eps) --------------------
// writes ctx directly as bf16 hi/lo planes for the out-projection GEMM.
__global__ void __launch_bounds__(256)
attn_out_kernel()
{
    __shared__ float Ss[DD][68];
    __shared__ float Qt[DD][68];   // Qt[k][l] (transposed)
    __shared__ float Zs[DD];

    const int bh = blockIdx.x;
    const int b  = bh >> 4, h = bh & 15;
    const int l0 = blockIdx.y * 64;
    const int tid = threadIdx.x;

    const float* Sp = g_S + (size_t)bh * DD * DD;
    const float* Qp = g_phiQ + (size_t)b * LL * EE + h * DD;

    for (int idx = tid; idx < DD * DD; idx += 256) {
        int r = idx >> 6, c = idx & 63;
        Ss[r][c] = Sp[idx];
        Qt[c][r] = Qp[(size_t)(l0 + r) * EE + c];
    }
    if (tid < DD) Zs[tid] = g_Z[bh * DD + tid];
    __syncthreads();

    const int tx = tid & 15, ty = tid >> 4;
    float num[4][4];
    float den[4] = {0.f, 0.f, 0.f, 0.f};
    #pragma unroll
    for (int i = 0; i < 4; i++)
        #pragma unroll
        for (int j = 0; j < 4; j++) num[i][j] = 0.f;

    #pragma unroll 8
    for (int k = 0; k < DD; k++) {
        float4 q = *(const float4*)&Qt[k][ty * 4];
        float4 s = *(const float4*)&Ss[k][tx * 4];
        float  z = Zs[k];
        float qa[4] = {q.x, q.y, q.z, q.w};
        float sa[4] = {s.x, s.y, s.z, s.w};
        #pragma unroll
        for (int i = 0; i < 4; i++) {
            #pragma unroll
            for (int j = 0; j < 4; j++) num[i][j] += qa[i] * sa[j];
            den[i] += qa[i] * z;
        }
    }

    #pragma unroll
    for (int i = 0; i < 4; i++) {
        float inv = 1.f / (den[i] + 1e-6f);
        uint32_t hp[2], lp[2];
        #pragma unroll
        for (int p = 0; p < 2; p++) {
            float x0 = num[i][2*p]   * inv;
            float x1 = num[i][2*p+1] * inv;
            __nv_bfloat16 h0, l0v, h1, l1v;
            bsplit(x0, h0, l0v);
            bsplit(x1, h1, l1v);
            hp[p] = ((uint32_t)__bfloat16_as_ushort(h1) << 16) | __bfloat16_as_ushort(h0);
            lp[p] = ((uint32_t)__bfloat16_as_ushort(l1v) << 16) | __bfloat16_as_ushort(l0v);
        }
        size_t idx = (size_t)(b * LL + l0 + ty * 4 + i) * EE + h * DD + tx * 4;
        *(uint2*)(g_Chi + idx) = make_uint2(hp[0], hp[1]);
        *(uint2*)(g_Clo + idx) = make_uint2(lp[0], lp[1]);
    }
}

// ---------------------------------------------------------------------------
extern "C" void kernel_launch(void* const* d_in, const int* in_sizes, int n_in,
                              void* d_out, int out_size)
{
    const float* X  = (const float*)d_in[0];
    const float* Wq = (const float*)d_in[1];
    const float* bq = (const float*)d_in[2];
    const float* Wk = (const float*)d_in[3];
    const float* bk = (const float*)d_in[4];
    const float* Wv = (const float*)d_in[5];
    const float* bv = (const float*)d_in[6];
    const float* Wo = (const float*)d_in[7];
    const float* bo = (const float*)d_in[8];
    float* out = (float*)d_out;

    cudaFuncSetAttribute(qkv_mma_kernel, cudaFuncAttributeMaxDynamicSharedMemorySize, SMEM_BYTES);
    cudaFuncSetAttribute(out_mma_kernel, cudaFuncAttributeMaxDynamicSharedMemorySize, SMEM_BYTES);

    // split X and weights into bf16 hi/lo planes
    split_kernel<<<(MM * EE) / 1024, 256>>>(X,  0, MM * EE);
    split_kernel<<<(EE * EE) / 1024, 256>>>(Wq, 1, EE * EE);
    split_kernel<<<(EE * EE) / 1024, 256>>>(Wk, 2, EE * EE);
    split_kernel<<<(EE * EE) / 1024, 256>>>(Wv, 3, EE * EE);
    split_kernel<<<(EE * EE) / 1024, 256>>>(Wo, 4, EE * EE);

    dim3 gqkv(EE / BN, MM / BM, 3);
    qkv_mma_kernel<<<gqkv, GT, SMEM_BYTES>>>(bq, bk, bv);

    kv_state_mma_kernel<<<dim3(BH, LSPLIT), 128>>>();
    reduce_kernel<<<(BH * DD * DD + 255) / 256, 256>>>();
    attn_out_kernel<<<dim3(BH, LL / 64), 256>>>();

    dim3 gout(EE / BN, MM / BM, 1);
    out_mma_kernel<<<gout, GT, SMEM_BYTES>>>(bo, out);
}

// round 14
// speedup vs baseline: 2.7447x; 1.0186x over previous
#include <cuda_runtime.h>
#include <cuda_bf16.h>
#include <cstdint>
#include <math.h>

// Problem dims (fixed by the reference)
#define BB 4
#define LL 4096
#define EE 1024
#define HH 16
#define DD 64
#define BH (BB*HH)       // 64
#define MM (BB*LL)       // 16384
#define LSPLIT 8

// GEMM tiling (bf16 split mma.sync)
#define BM 128
#define BN 128
#define BK 32                         // fp32-equivalent K per stage
#define PITCH 20                      // u32 per smem row (80B): conflict-free + 16B aligned
#define PLANE_U32 (128*PITCH)         // one operand plane (hi or lo): 10240 B
#define STAGE_U32 (4*PLANE_U32)       // Ahi,Alo,Bhi,Blo
#define SMEM_BYTES (2*STAGE_U32*4)    // double buffered = 81920 B
#define GT 256

// kv_state MMA tiling
#define KPITCH 40                     // bf16 per smem row (80B) — same bank rotation
#define KPB 80                        // bytes per row
#define KPLANE (64*KPITCH)            // bf16 units per plane
#define KV_LC (LL/LSPLIT)             // 512 l per split
#define KV_NST (KV_LC/32)             // 16 stages

// ---------------- scratch ---------------------------------------------------
__device__ __nv_bfloat16 g_Xhi[MM*EE], g_Xlo[MM*EE];
__device__ __nv_bfloat16 g_Whi[4][EE*EE], g_Wlo[4][EE*EE];   // q,k,v,o
__device__ __nv_bfloat16 g_Chi[MM*EE], g_Clo[MM*EE];         // ctx split
__device__ __nv_bfloat16 g_KThi[BH*DD*LL], g_KTlo[BH*DD*LL]; // phiK transposed [bh][d][l]
__device__ __nv_bfloat16 g_VThi[BH*DD*LL], g_VTlo[BH*DD*LL]; // V transposed
__device__ float g_phiQ[MM*EE];
__device__ float g_S  [BH*DD*DD];
__device__ float g_Z  [BH*DD];
__device__ float g_Spart[LSPLIT*BH*DD*DD];
__device__ float g_Zpart[LSPLIT*BH*DD];

// ---------------- helpers ---------------------------------------------------
__device__ __forceinline__ void cpasync16(uint32_t dst, const void* src){
    asm volatile("cp.async.cg.shared.global [%0], [%1], 16;" :: "r"(dst), "l"(src) : "memory");
}
__device__ __forceinline__ void cp_commit(){
    asm volatile("cp.async.commit_group;" ::: "memory");
}
template<int N> __device__ __forceinline__ void cp_wait(){
    asm volatile("cp.async.wait_group %0;" :: "n"(N) : "memory");
}
__device__ __forceinline__ uint32_t smem_u32(const void* p){
    uint32_t a;
    asm("{ .reg .u64 t; cvta.to.shared.u64 t, %1; cvt.u32.u64 %0, t; }" : "=r"(a) : "l"(p));
    return a;
}
__device__ __forceinline__ void mma_bf16(float* c, const uint32_t* a, const uint32_t* b){
    asm volatile("mma.sync.aligned.m16n8k16.row.col.f32.bf16.bf16.f32 "
        "{%0,%1,%2,%3}, {%4,%5,%6,%7}, {%8,%9}, {%0,%1,%2,%3};"
        : "+f"(c[0]), "+f"(c[1]), "+f"(c[2]), "+f"(c[3])
        : "r"(a[0]), "r"(a[1]), "r"(a[2]), "r"(a[3]), "r"(b[0]), "r"(b[1]));
}
__device__ __forceinline__ void ldsm_x4(uint32_t* r, uint32_t addr){
    asm volatile("ldmatrix.sync.aligned.m8n8.x4.shared.b16 {%0,%1,%2,%3}, [%4];"
        : "=r"(r[0]), "=r"(r[1]), "=r"(r[2]), "=r"(r[3]) : "r"(addr));
}
__device__ __forceinline__ void bsplit(float x, __nv_bfloat16& h, __nv_bfloat16& l){
    h = __float2bfloat16(x);
    l = __float2bfloat16(x - __bfloat162float(h));
}

// ---------------- fp32 -> bf16 hi/lo split (single merged launch) -----------
// blocks [0,16384): X ; then 4x1024 blocks for Wq,Wk,Wv,Wo
__global__ void __launch_bounds__(256)
split_all_kernel(const float* __restrict__ X,
                 const float* __restrict__ Wq, const float* __restrict__ Wk,
                 const float* __restrict__ Wv, const float* __restrict__ Wo)
{
    int blk = blockIdx.x;
    const float* src;
    __nv_bfloat16 *hi, *lo;
    int base;
    if (blk < 16384) {
        src = X; hi = g_Xhi; lo = g_Xlo; base = blk;
    } else {
        int w  = (blk - 16384) >> 10;
        int rb = (blk - 16384) & 1023;
        src = (w == 0) ? Wq : (w == 1) ? Wk : (w == 2) ? Wv : Wo;
        hi = g_Whi[w]; lo = g_Wlo[w]; base = rb;
    }
    int i = (base * 256 + threadIdx.x) * 4;
    float4 v = *(const float4*)(src + i);
    float x[4] = {v.x, v.y, v.z, v.w};
    uint32_t hp[2], lp[2];
    #pragma unroll
    for (int p = 0; p < 2; p++) {
        __nv_bfloat16 h0, l0, h1, l1;
        bsplit(x[2*p],   h0, l0);
        bsplit(x[2*p+1], h1, l1);
        hp[p] = ((uint32_t)__bfloat16_as_ushort(h1) << 16) | __bfloat16_as_ushort(h0);
        lp[p] = ((uint32_t)__bfloat16_as_ushort(l1) << 16) | __bfloat16_as_ushort(l0);
    }
    *(uint2*)(hi + i) = make_uint2(hp[0], hp[1]);
    *(uint2*)(lo + i) = make_uint2(lp[0], lp[1]);
}

// ---------------- bf16-split tensor-core GEMM body --------------------------
// mode 0: fp32 out; 1: elu+1 fp32 out; 2: elu+1 -> transposed hi/lo; 3: plain -> transposed hi/lo
__device__ __forceinline__ void load_tile(uint32_t st,
                                          const __nv_bfloat16* __restrict__ Ahi,
                                          const __nv_bfloat16* __restrict__ Alo,
                                          const __nv_bfloat16* __restrict__ Bhi,
                                          const __nv_bfloat16* __restrict__ Blo,
                                          int m0, int n0, int k0, int tid)
{
    #pragma unroll
    for (int t = 0; t < 2; t++) {
        int p   = tid + GT * t;          // 0..511
        int row = p >> 2;                // 0..127
        int cg  = p & 3;                 // 16B chunk within 64B row (32 bf16)
        uint32_t off = (uint32_t)(row * PITCH * 4 + cg * 16);
        size_t ga = (size_t)(m0 + row) * EE + k0 + cg * 8;
        size_t gb = (size_t)(n0 + row) * EE + k0 + cg * 8;
        cpasync16(st + off,                    Ahi + ga);
        cpasync16(st + PLANE_U32*4   + off,    Alo + ga);
        cpasync16(st + 2*PLANE_U32*4 + off,    Bhi + gb);
        cpasync16(st + 3*PLANE_U32*4 + off,    Blo + gb);
    }
}

__device__ __forceinline__ void mma_gemm(const __nv_bfloat16* __restrict__ Ahi,
                                         const __nv_bfloat16* __restrict__ Alo,
                                         const __nv_bfloat16* __restrict__ Bhi,
                                         const __nv_bfloat16* __restrict__ Blo,
                                         const float* __restrict__ bias,
                                         float* __restrict__ C,
                                         __nv_bfloat16* __restrict__ Thi,
                                         __nv_bfloat16* __restrict__ Tlo,
                                         int mode)
{
    extern __shared__ uint32_t smem[];
    const uint32_t sbase = smem_u32(smem);

    const int tid  = threadIdx.x;
    const int wid  = tid >> 5;
    const int lane = tid & 31;
    const int g    = lane >> 2;
    const int tg   = lane & 3;
    const int m0   = blockIdx.y * BM;
    const int n0   = blockIdx.x * BN;
    const int warpM = (wid >> 2) * 64;
    const int warpN = (wid & 3) * 32;

    const int a_row = lane & 15;
    const int a_col = (lane >> 4) * 16;
    const int b_row = lane & 7;
    const int b_sel = ((lane >> 3) & 1) * 16;
    const int b_pair = (lane >> 4);

    float acc[4][4][4];
    #pragma unroll
    for (int i = 0; i < 4; i++)
        #pragma unroll
        for (int j = 0; j < 4; j++)
            #pragma unroll
            for (int r = 0; r < 4; r++) acc[i][j][r] = 0.f;

    load_tile(sbase, Ahi, Alo, Bhi, Blo, m0, n0, 0, tid);
    cp_commit();

    const int NIT = EE / BK;             // 32
    for (int it = 0; it < NIT; it++) {
        cp_wait<0>();                    // current stage (it&1) landed
        __syncthreads();                 // all warps done with prev compute; data visible
        if (it + 1 < NIT) {              // prefetch next stage into the other buffer
            load_tile(sbase + ((it + 1) & 1) * STAGE_U32 * 4,
                      Ahi, Alo, Bhi, Blo, m0, n0, (it + 1) * BK, tid);
            cp_commit();
        }

        const uint32_t stage = sbase + (it & 1) * STAGE_U32 * 4;
        const uint32_t A_hi = stage;
        const uint32_t A_lo = stage + PLANE_U32 * 4;
        const uint32_t B_hi = stage + 2 * PLANE_U32 * 4;
        const uint32_t B_lo = stage + 3 * PLANE_U32 * 4;

        #pragma unroll
        for (int kb = 0; kb < 2; kb++) {
            const uint32_t kbyte = kb * 32;
            uint32_t ah[4][4], al[4][4], bh[4][2], bl[4][2];

            #pragma unroll
            for (int mt = 0; mt < 4; mt++) {
                uint32_t aoff = (uint32_t)(warpM + mt * 16 + a_row) * (PITCH * 4)
                                + kbyte + a_col;
                ldsm_x4(ah[mt], A_hi + aoff);
                ldsm_x4(al[mt], A_lo + aoff);
            }
            #pragma unroll
            for (int p = 0; p < 2; p++) {
                uint32_t boff = (uint32_t)(warpN + (2 * p + b_pair) * 8 + b_row) * (PITCH * 4)
                                + kbyte + b_sel;
                uint32_t th[4], tl[4];
                ldsm_x4(th, B_hi + boff);
                ldsm_x4(tl, B_lo + boff);
                bh[2*p][0] = th[0]; bh[2*p][1] = th[1];
                bh[2*p+1][0] = th[2]; bh[2*p+1][1] = th[3];
                bl[2*p][0] = tl[0]; bl[2*p][1] = tl[1];
                bl[2*p+1][0] = tl[2]; bl[2*p+1][1] = tl[3];
            }

            #pragma unroll
            for (int mt = 0; mt < 4; mt++)
                #pragma unroll
                for (int nt = 0; nt < 4; nt++) {
                    mma_bf16(acc[mt][nt], ah[mt], bh[nt]);
                    mma_bf16(acc[mt][nt], ah[mt], bl[nt]);
                    mma_bf16(acc[mt][nt], al[mt], bh[nt]);
                }
        }
    }

    // epilogue
    #pragma unroll
    for (int mt = 0; mt < 4; mt++) {
        int row = m0 + warpM + mt * 16 + g;
        #pragma unroll
        for (int nt = 0; nt < 4; nt++) {
            int col = n0 + warpN + nt * 8 + 2 * tg;
            float b0 = bias[col], b1 = bias[col + 1];
            float v0 = acc[mt][nt][0] + b0;
            float v1 = acc[mt][nt][1] + b1;
            float v2 = acc[mt][nt][2] + b0;
            float v3 = acc[mt][nt][3] + b1;
            if (mode == 1 || mode == 2) {
                v0 = (v0 > 0.f) ? (v0 + 1.f) : expf(v0);
                v1 = (v1 > 0.f) ? (v1 + 1.f) : expf(v1);
                v2 = (v2 > 0.f) ? (v2 + 1.f) : expf(v2);
                v3 = (v3 > 0.f) ? (v3 + 1.f) : expf(v3);
            }
            if (mode <= 1) {
                *(float2*)&C[(size_t)row * EE + col]       = make_float2(v0, v1);
                *(float2*)&C[(size_t)(row + 8) * EE + col] = make_float2(v2, v3);
            } else {
                // transposed bf16 hi/lo: dst[(b*1024 + col)][l], l = row % LL
                int bi = row >> 12;
                int l  = row & (LL - 1);
                size_t p0 = ((size_t)(bi * 1024 + col)) * LL + l;
                size_t p1 = p0 + LL;   // col+1
                __nv_bfloat16 h, lo;
                bsplit(v0, h, lo); Thi[p0]     = h; Tlo[p0]     = lo;
                bsplit(v2, h, lo); Thi[p0 + 8] = h; Tlo[p0 + 8] = lo;
                bsplit(v1, h, lo); Thi[p1]     = h; Tlo[p1]     = lo;
                bsplit(v3, h, lo); Thi[p1 + 8] = h; Tlo[p1 + 8] = lo;
            }
        }
    }
}

// grid (8, 128, 3): z selects Q/K/V
__global__ void __launch_bounds__(GT)
qkv_mma_kernel(const float* __restrict__ bq,
               const float* __restrict__ bk,
               const float* __restrict__ bv)
{
    int z = blockIdx.z;
    if (z == 0)
        mma_gemm(g_Xhi, g_Xlo, g_Whi[0], g_Wlo[0], bq, g_phiQ, nullptr, nullptr, 1);
    else if (z == 1)
        mma_gemm(g_Xhi, g_Xlo, g_Whi[1], g_Wlo[1], bk, nullptr, g_KThi, g_KTlo, 2);
    else
        mma_gemm(g_Xhi, g_Xlo, g_Whi[2], g_Wlo[2], bv, nullptr, g_VThi, g_VTlo, 3);
}

__global__ void __launch_bounds__(GT)
out_mma_kernel(const float* __restrict__ bo, float* __restrict__ out)
{
    mma_gemm(g_Chi, g_Clo, g_Whi[3], g_Wlo[3], bo, out, nullptr, nullptr, 0);
}

// ---------------- KV state on tensor cores ----------------------------------
// S_part[bh][i][j] = sum_{l in split} phiK[l,i] * V[l,j], via transposed hi/lo planes.
__global__ void __launch_bounds__(128)
kv_state_mma_kernel()
{
    __shared__ __nv_bfloat16 sm[2][4 * KPLANE];

    const int bh  = blockIdx.x;
    const int p   = blockIdx.y;
    const int tid = threadIdx.x;
    const int wid = tid >> 5;
    const int lane = tid & 31;
    const int g   = lane >> 2;
    const int tg  = lane & 3;
    const int a_row = lane & 15;
    const int a_col = (lane >> 4) * 16;
    const int b_row = lane & 7;
    const int b_sel = ((lane >> 3) & 1) * 16;
    const int b_pair = lane >> 4;

    const size_t gbase = (size_t)bh * DD * LL + (size_t)p * KV_LC;
    const __nv_bfloat16* srcs[4] = { g_KThi + gbase, g_KTlo + gbase,
                                     g_VThi + gbase, g_VTlo + gbase };

    float acc[4][2][4];
    #pragma unroll
    for (int i = 0; i < 4; i++)
        #pragma unroll
        for (int j = 0; j < 2; j++)
            #pragma unroll
            for (int r = 0; r < 4; r++) acc[i][j][r] = 0.f;
    float zacc = 0.f;

    auto issue_load = [&](int buf, int s){
        uint32_t dst0 = smem_u32(&sm[buf][0]);
        int l0 = s * 32;
        #pragma unroll
        for (int t = 0; t < 8; t++) {
            int q = tid + 128 * t;           // 0..1023
            int plane = q >> 8;
            int rem = q & 255;
            int row = rem >> 2;
            int cg = rem & 3;
            const __nv_bfloat16* src = srcs[plane] + (size_t)row * LL + l0 + cg * 8;
            uint32_t dst = dst0 + (uint32_t)(plane * KPLANE + row * KPITCH + cg * 8) * 2;
            cpasync16(dst, src);
        }
    };

    issue_load(0, 0);
    cp_commit();

    for (int s = 0; s < KV_NST; s++) {
        cp_wait<0>();
        __syncthreads();
        if (s + 1 < KV_NST) {
            issue_load((s + 1) & 1, s + 1);
            cp_commit();
        }

        uint32_t sb = smem_u32(&sm[s & 1][0]);
        uint32_t Khi = sb;
        uint32_t Klo = sb + KPLANE * 2;
        uint32_t Vhi = sb + 2 * KPLANE * 2;
        uint32_t Vlo = sb + 3 * KPLANE * 2;

        #pragma unroll
        for (int kb = 0; kb < 2; kb++) {
            uint32_t kbyte = kb * 32;
            uint32_t ah[4][4], al[4][4], bhf[2][2], blf[2][2];
            #pragma unroll
            for (int mt = 0; mt < 4; mt++) {
                uint32_t aoff = (uint32_t)(mt * 16 + a_row) * KPB + kbyte + a_col;
                ldsm_x4(ah[mt], Khi + aoff);
                ldsm_x4(al[mt], Klo + aoff);
            }
            uint32_t boff = (uint32_t)(wid * 16 + b_pair * 8 + b_row) * KPB + kbyte + b_sel;
            uint32_t th[4], tl[4];
            ldsm_x4(th, Vhi + boff);
            ldsm_x4(tl, Vlo + boff);
            bhf[0][0] = th[0]; bhf[0][1] = th[1];
            bhf[1][0] = th[2]; bhf[1][1] = th[3];
            blf[0][0] = tl[0]; blf[0][1] = tl[1];
            blf[1][0] = tl[2]; blf[1][1] = tl[3];

            #pragma unroll
            for (int mt = 0; mt < 4; mt++)
                #pragma unroll
                for (int nt = 0; nt < 2; nt++) {
                    mma_bf16(acc[mt][nt], ah[mt], bhf[nt]);
                    mma_bf16(acc[mt][nt], ah[mt], blf[nt]);
                    mma_bf16(acc[mt][nt], al[mt], bhf[nt]);
                }
        }

        // deterministic Z partial: threads 0..63 sum phiK row d over this stage
        if (tid < DD) {
            const __nv_bfloat16* kh = &sm[s & 1][tid * KPITCH];
            const __nv_bfloat16* kl = kh + KPLANE;
            #pragma unroll
            for (int i = 0; i < 32; i++)
                zacc += __bfloat162float(kh[i]) + __bfloat162float(kl[i]);
        }
    }

    float* Sp = g_Spart + ((size_t)p * BH + bh) * DD * DD;
    #pragma unroll
    for (int mt = 0; mt < 4; mt++) {
        int m = mt * 16 + g;
        #pragma unroll
        for (int nt = 0; nt < 2; nt++) {
            int n = wid * 16 + nt * 8 + 2 * tg;
            *(float2*)&Sp[m * DD + n]       = make_float2(acc[mt][nt][0], acc[mt][nt][1]);
            *(float2*)&Sp[(m + 8) * DD + n] = make_float2(acc[mt][nt][2], acc[mt][nt][3]);
        }
    }
    if (tid < DD)
        g_Zpart[((size_t)p * BH + bh) * DD + tid] = zacc;
}

__global__ void __launch_bounds__(256)
reduce_kernel()
{
    int idx = blockIdx.x * 256 + threadIdx.x;
    if (idx < BH * DD * DD) {
        float s = 0.f;
        #pragma unroll
        for (int pp = 0; pp < LSPLIT; pp++) s += g_Spart[(size_t)pp * BH * DD * DD + idx];
        g_S[idx] = s;
    }
    if (idx < BH * DD) {
        float s = 0.f;
        #pragma unroll
        for (int pp = 0; pp < LSPLIT; pp++) s += g_Zpart[(size_t)pp * BH * DD + idx];
        g_Z[idx] = s;
    }
}

// ---------------- context = (phiQ @ S) / (phiQ . Z + eps) --------------------
// writes ctx directly as bf16 hi/lo planes for the out-projection GEMM.
__global__ void __launch_bounds__(256)
attn_out_kernel()
{
    __shared__ float Ss[DD][68];
    __shared__ float Qt[DD][68];   // Qt[k][l] (transposed)
    __shared__ float Zs[DD];

    const int bh = blockIdx.x;
    const int b  = bh >> 4, h = bh & 15;
    const int l0 = blockIdx.y * 64;
    const int tid = threadIdx.x;

    const float* Sp = g_S + (size_t)bh * DD * DD;
    const float* Qp = g_phiQ + (size_t)b * LL * EE + h * DD;

    for (int idx = tid; idx < DD * DD; idx += 256) {
        int r = idx >> 6, c = idx & 63;
        Ss[r][c] = Sp[idx];
        Qt[c][r] = Qp[(size_t)(l0 + r) * EE + c];
    }
    if (tid < DD) Zs[tid] = g_Z[bh * DD + tid];
    __syncthreads();

    const int tx = tid & 15, ty = tid >> 4;
    float num[4][4];
    float den[4] = {0.f, 0.f, 0.f, 0.f};
    #pragma unroll
    for (int i = 0; i < 4; i++)
        #pragma unroll
        for (int j = 0; j < 4; j++) num[i][j] = 0.f;

    #pragma unroll 8
    for (int k = 0; k < DD; k++) {
        float4 q = *(const float4*)&Qt[k][ty * 4];
        float4 s = *(const float4*)&Ss[k][tx * 4];
        float  z = Zs[k];
        float qa[4] = {q.x, q.y, q.z, q.w};
        float sa[4] = {s.x, s.y, s.z, s.w};
        #pragma unroll
        for (int i = 0; i < 4; i++) {
            #pragma unroll
            for (int j = 0; j < 4; j++) num[i][j] += qa[i] * sa[j];
            den[i] += qa[i] * z;
        }
    }

    #pragma unroll
    for (int i = 0; i < 4; i++) {
        float inv = 1.f / (den[i] + 1e-6f);
        uint32_t hp[2], lp[2];
        #pragma unroll
        for (int p = 0; p < 2; p++) {
            float x0 = num[i][2*p]   * inv;
            float x1 = num[i][2*p+1] * inv;
            __nv_bfloat16 h0, l0v, h1, l1v;
            bsplit(x0, h0, l0v);
            bsplit(x1, h1, l1v);
            hp[p] = ((uint32_t)__bfloat16_as_ushort(h1) << 16) | __bfloat16_as_ushort(h0);
            lp[p] = ((uint32_t)__bfloat16_as_ushort(l1v) << 16) | __bfloat16_as_ushort(l0v);
        }
        size_t idx = (size_t)(b * LL + l0 + ty * 4 + i) * EE + h * DD + tx * 4;
        *(uint2*)(g_Chi + idx) = make_uint2(hp[0], hp[1]);
        *(uint2*)(g_Clo + idx) = make_uint2(lp[0], lp[1]);
    }
}

// ---------------------------------------------------------------------------
extern "C" void kernel_launch(void* const* d_in, const int* in_sizes, int n_in,
                              void* d_out, int out_size)
{
    const float* X  = (const float*)d_in[0];
    const float* Wq = (const float*)d_in[1];
    const float* bq = (const float*)d_in[2];
    const float* Wk = (const float*)d_in[3];
    const float* bk = (const float*)d_in[4];
    const float* Wv = (const float*)d_in[5];
    const float* bv = (const float*)d_in[6];
    const float* Wo = (const float*)d_in[7];
    const float* bo = (const float*)d_in[8];
    float* out = (float*)d_out;

    cudaFuncSetAttribute(qkv_mma_kernel, cudaFuncAttributeMaxDynamicSharedMemorySize, SMEM_BYTES);
    cudaFuncSetAttribute(out_mma_kernel, cudaFuncAttributeMaxDynamicSharedMemorySize, SMEM_BYTES);

    // one merged split launch: X + 4 weight matrices
    split_all_kernel<<<16384 + 4 * 1024, 256>>>(X, Wq, Wk, Wv, Wo);

    dim3 gqkv(EE / BN, MM / BM, 3);
    qkv_mma_kernel<<<gqkv, GT, SMEM_BYTES>>>(bq, bk, bv);

    kv_state_mma_kernel<<<dim3(BH, LSPLIT), 128>>>();
    reduce_kernel<<<(BH * DD * DD + 255) / 256, 256>>>();
    attn_out_kernel<<<dim3(BH, LL / 64), 256>>>();

    dim3 gout(EE / BN, MM / BM, 1);
    out_mma_kernel<<<gout, GT, SMEM_BYTES>>>(bo, out);
}